// round 2
// baseline (speedup 1.0000x reference)
#include <cuda_runtime.h>
#include <cuda_bf16.h>
#include <cstdint>
#include <cstdio>

// ---------------------------------------------------------------------------
// Problem constants
// ---------------------------------------------------------------------------
#define BATCH   4
#define NPTS    16384
#define CIN     128
#define NPOINT  1024
#define FG_NS   512
#define TOPK_K  2048
#define NSAMP   32
#define NCOLS2D (BATCH * NPOINT * NSAMP)   // 131072
#define NCOLS1D (BATCH * NPTS)             // 65536

// output layout (floats)
#define OFS_XYZ    0
#define OFS_FEAT   12288
#define OFS_IDX    (12288 + 1048576)
#define OFS_SCORES (12288 + 1048576 + 4096)

// scratch layout (floats within g_scratch)
#define O_Y1D     0ull                          // 4*64*16384      = 4194304
#define O_X       4194304ull                    // 131*131072     = 17170432
#define O_Y1      21364736ull                   // 128*131072     = 16777216
#define O_Y2      38141952ull                   // 128*131072
#define O_Y3      54919168ull                   // 256*131072     = 33554432
#define O_MARGIN  88473600ull                   // 65536
#define O_NEWXYZ  88539136ull                   // 12288
#define O_FGMASK  88551424ull                   // 65536 ints
#define O_INDICES 88616960ull                   // 4096 ints
#define O_BALL    88621056ull                   // 131072 ints
#define O_FPSPID  88752128ull                   // 8*14336 ints
#define SCRATCH_FLOATS 88866816ull

__device__ float g_scratch[SCRATCH_FLOATS];

__device__ double g_sum[4][256];
__device__ double g_sumsq[4][256];
__device__ float  g_aff_a[4][256];
__device__ float  g_aff_c[4][256];

// ---------------------------------------------------------------------------
// util kernels
// ---------------------------------------------------------------------------
__global__ void zero_stats_kernel() {
    int t = threadIdx.x;
    double* s  = &g_sum[0][0];
    double* s2 = &g_sumsq[0][0];
    for (int i = t; i < 4 * 256; i += blockDim.x) { s[i] = 0.0; s2[i] = 0.0; }
}

// ---------------------------------------------------------------------------
// SGEMM: C[M x Ncols] = A[M x K] * B[K x Ncols]
// bmode==1: B is features [BATCH][128][NPTS]; column col -> b=col>>14, n=col&16383
// affLayer>=0: B element transformed by relu(a[k]*v + c[k]) on load
// ---------------------------------------------------------------------------
#define GBM 128
#define GBN 128
#define GBK 16
__global__ void __launch_bounds__(256) gemm_kernel(
    const float* __restrict__ A, const float* __restrict__ B, float* __restrict__ C,
    int M, int K, int Ncols, int affLayer, int bmode)
{
    __shared__ float As[GBK][GBM + 1];
    __shared__ float Bs[GBK][GBN];
    int tid = threadIdx.x;
    int tx = tid & 15, ty = tid >> 4;
    int rowBase = blockIdx.y * GBM;
    int colBase = blockIdx.x * GBN;
    float acc[8][8];
#pragma unroll
    for (int i = 0; i < 8; i++)
#pragma unroll
        for (int j = 0; j < 8; j++) acc[i][j] = 0.f;

    int ktiles = (K + GBK - 1) / GBK;
    for (int kt = 0; kt < ktiles; kt++) {
        int k0 = kt * GBK;
        // load A tile (coalesced along K)
#pragma unroll
        for (int l = 0; l < 8; l++) {
            int i = l * 256 + tid;
            int r = i >> 4;
            int kk = i & 15;
            int gr = rowBase + r, gk = k0 + kk;
            As[kk][r] = (gr < M && gk < K) ? A[gr * K + gk] : 0.f;
        }
        // load B tile as float4
#pragma unroll
        for (int l = 0; l < 2; l++) {
            int i = l * 256 + tid;
            int kk = i >> 5;
            int c4 = i & 31;
            int gk = k0 + kk;
            float4 v = make_float4(0.f, 0.f, 0.f, 0.f);
            if (gk < K) {
                int gc = colBase + c4 * 4;
                const float* src;
                if (bmode == 1) {
                    int bb = gc >> 14; int n = gc & 16383;
                    src = B + (((size_t)bb * 128 + gk) << 14) + n;
                } else {
                    src = B + (size_t)gk * Ncols + gc;
                }
                v = *(const float4*)src;
                if (affLayer >= 0) {
                    float a = g_aff_a[affLayer][gk], c = g_aff_c[affLayer][gk];
                    v.x = fmaxf(fmaf(a, v.x, c), 0.f);
                    v.y = fmaxf(fmaf(a, v.y, c), 0.f);
                    v.z = fmaxf(fmaf(a, v.z, c), 0.f);
                    v.w = fmaxf(fmaf(a, v.w, c), 0.f);
                }
            }
            *(float4*)&Bs[kk][c4 * 4] = v;
        }
        __syncthreads();
#pragma unroll
        for (int kk = 0; kk < GBK; kk++) {
            float ra[8], rb[8];
#pragma unroll
            for (int i = 0; i < 8; i++) ra[i] = As[kk][ty * 8 + i];
#pragma unroll
            for (int j = 0; j < 8; j++) rb[j] = Bs[kk][tx * 8 + j];
#pragma unroll
            for (int i = 0; i < 8; i++)
#pragma unroll
                for (int j = 0; j < 8; j++)
                    acc[i][j] = fmaf(ra[i], rb[j], acc[i][j]);
        }
        __syncthreads();
    }
#pragma unroll
    for (int i = 0; i < 8; i++) {
        int gr = rowBase + ty * 8 + i;
        if (gr < M) {
            float* dst = C + (size_t)gr * Ncols + colBase + tx * 8;
            *(float4*)dst       = make_float4(acc[i][0], acc[i][1], acc[i][2], acc[i][3]);
            *(float4*)(dst + 4) = make_float4(acc[i][4], acc[i][5], acc[i][6], acc[i][7]);
        }
    }
}

// ---------------------------------------------------------------------------
// per-channel sum/sumsq reduction (double accumulation)
// ---------------------------------------------------------------------------
__global__ void stats_kernel(const float* __restrict__ Y, int Ncols, int layer)
{
    int m = blockIdx.x;
    double s = 0.0, s2 = 0.0;
    for (int i = blockIdx.y * blockDim.x + threadIdx.x; i < Ncols; i += gridDim.y * blockDim.x) {
        float v = Y[(size_t)m * Ncols + i];
        s += (double)v;
        s2 += (double)v * (double)v;
    }
    int lane = threadIdx.x & 31, wid = threadIdx.x >> 5;
#pragma unroll
    for (int off = 16; off; off >>= 1) {
        s  += __shfl_down_sync(0xFFFFFFFFu, s, off);
        s2 += __shfl_down_sync(0xFFFFFFFFu, s2, off);
    }
    __shared__ double shs[8], shs2[8];
    if (lane == 0) { shs[wid] = s; shs2[wid] = s2; }
    __syncthreads();
    if (wid == 0) {
        s  = (lane < 8) ? shs[lane]  : 0.0;
        s2 = (lane < 8) ? shs2[lane] : 0.0;
#pragma unroll
        for (int off = 4; off; off >>= 1) {
            s  += __shfl_down_sync(0xFFFFFFFFu, s, off);
            s2 += __shfl_down_sync(0xFFFFFFFFu, s2, off);
        }
        if (lane == 0) {
            atomicAdd(&g_sum[layer][m], s);
            atomicAdd(&g_sumsq[layer][m], s2);
        }
    }
}

__global__ void finalize_kernel(int M, const float* __restrict__ g,
                                const float* __restrict__ beta, int layer, double cnt)
{
    int m = threadIdx.x;
    if (m < M) {
        double mu = g_sum[layer][m] / cnt;
        double var = g_sumsq[layer][m] / cnt - mu * mu;
        float a = g[m] * rsqrtf((float)var + 1e-5f);
        g_aff_a[layer][m] = a;
        g_aff_c[layer][m] = beta[m] - (float)mu * a;
    }
}

// ---------------------------------------------------------------------------
// mask head: scores + margin  (reads raw y1d, applies layer-0 BN+relu)
// ---------------------------------------------------------------------------
__global__ void maskhead_kernel(const float* __restrict__ y1d,
                                const float* __restrict__ fw2,
                                const float* __restrict__ fbias2,
                                float* __restrict__ outScores,
                                float* __restrict__ margin)
{
    int col = blockIdx.x * blockDim.x + threadIdx.x;   // 65536
    int b = col >> 14, n = col & 16383;
    float s0 = fbias2[0], s1 = fbias2[1];
#pragma unroll 4
    for (int c = 0; c < 64; c++) {
        float a = g_aff_a[0][c], cc = g_aff_c[0][c];
        float v = fmaxf(fmaf(a, y1d[(size_t)c * NCOLS1D + col], cc), 0.f);
        s0 = fmaf(fw2[c], v, s0);
        s1 = fmaf(fw2[64 + c], v, s1);
    }
    outScores[b * 32768 + n]         = s0;
    outScores[b * 32768 + 16384 + n] = s1;
    float mx = fmaxf(s0, s1);
    float e0 = expf(s0 - mx), e1 = expf(s1 - mx);
    margin[col] = (e1 - e0) / (e0 + e1);
}

// ---------------------------------------------------------------------------
// exact top-2048 selection via 64-bit radix select (value desc, index asc)
// ---------------------------------------------------------------------------
__device__ __forceinline__ unsigned long long makeKey(float f, int i)
{
    unsigned u = __float_as_uint(f);
    u = (u & 0x80000000u) ? ~u : (u | 0x80000000u);
    return ((unsigned long long)u << 32) | (unsigned)(0xFFFFFFFFu - (unsigned)i);
}

__global__ void select_kernel(const float* __restrict__ margin, int* __restrict__ fgmask)
{
    __shared__ unsigned hist[256];
    __shared__ unsigned long long sprefix;
    __shared__ int skrem;
    int b = blockIdx.x, tid = threadIdx.x;
    const float* M = margin + b * NPTS;
    if (tid == 0) { sprefix = 0ull; skrem = TOPK_K; }
    __syncthreads();
    for (int pos = 56; pos >= 0; pos -= 8) {
        hist[tid] = 0;
        __syncthreads();
        unsigned long long pref = sprefix;
        for (int i = tid; i < NPTS; i += 256) {
            unsigned long long key = makeKey(M[i], i);
            bool act = (pos == 56) || ((key >> (pos + 8)) == (pref >> (pos + 8)));
            if (act) atomicAdd(&hist[(unsigned)(key >> pos) & 255u], 1u);
        }
        __syncthreads();
        if (tid == 0) {
            int k = skrem;
            int v = 255;
            while (v > 0 && (int)hist[v] < k) { k -= (int)hist[v]; v--; }
            skrem = k;
            sprefix = pref | ((unsigned long long)(unsigned)v << pos);
        }
        __syncthreads();
    }
    unsigned long long kth = sprefix;
    for (int i = tid; i < NPTS; i += 256)
        fgmask[b * NPTS + i] = (makeKey(M[i], i) >= kth) ? 1 : 0;
}

// ---------------------------------------------------------------------------
// masked FPS: 8 CTAs (batch x {fg,bg}); coords in SMEM, mind/pid in registers.
// Distances use rn intrinsics (no fma) to track XLA arithmetic; argmax ties
// broken by smallest original index (jnp.argmax semantics).
// ---------------------------------------------------------------------------
#define FPS_PT 14  // 14*1024 = 14336 = max masked count (bg)
__global__ void __launch_bounds__(1024) fps_kernel(
    const float* __restrict__ xyz, const int* __restrict__ fgmask,
    int* __restrict__ fpsPid, int* __restrict__ idxInt, float* __restrict__ idxOutF)
{
    extern __shared__ float sh[];
    float* xs = sh;
    float* ys = sh + 14336;
    float* zs = sh + 2 * 14336;
    __shared__ int scnt;
    __shared__ float rv[32];
    __shared__ int ri[32];
    __shared__ float ssx, ssy, ssz;

    int blk = blockIdx.x;
    int b = blk >> 1;
    int isFg = !(blk & 1);
    const float* X = xyz + (size_t)b * NPTS * 3;
    const int* Mk = fgmask + b * NPTS;
    int* pidbuf = fpsPid + blk * 14336;
    int tid = threadIdx.x;

    if (tid == 0) scnt = 0;
    __syncthreads();
    for (int i = tid; i < NPTS; i += 1024) {
        int m = Mk[i];
        if (!isFg) m = !m;
        if (m) {
            int pos = atomicAdd(&scnt, 1);
            xs[pos] = X[i * 3 + 0];
            ys[pos] = X[i * 3 + 1];
            zs[pos] = X[i * 3 + 2];
            pidbuf[pos] = i;
        }
    }
    __syncthreads();
    int cnt = scnt;

    float mind[FPS_PT];
    int pid[FPS_PT];
#pragma unroll
    for (int j = 0; j < FPS_PT; j++) {
        int slot = j * 1024 + tid;
        if (slot < cnt) { mind[j] = 1e10f; pid[j] = pidbuf[slot]; }
        else            { mind[j] = -3.0f; pid[j] = 0x7FFFFFFF; }
    }

    int lane = tid & 31, wid = tid >> 5;
    int outBase = b * NPOINT + (isFg ? 0 : FG_NS);
    int nIter = FG_NS; // 512 for both fg and bg (NPOINT - FG_NS == 512)

    for (int it = 0; it < nIter; it++) {
        float bv = -4.f;
        int bi = 0x7FFFFFFF;
#pragma unroll
        for (int j = 0; j < FPS_PT; j++) {
            float v = mind[j]; int i2 = pid[j];
            if (v > bv || (v == bv && i2 < bi)) { bv = v; bi = i2; }
        }
#pragma unroll
        for (int off = 16; off; off >>= 1) {
            float ov = __shfl_down_sync(0xFFFFFFFFu, bv, off);
            int   oi = __shfl_down_sync(0xFFFFFFFFu, bi, off);
            if (ov > bv || (ov == bv && oi < bi)) { bv = ov; bi = oi; }
        }
        if (lane == 0) { rv[wid] = bv; ri[wid] = bi; }
        __syncthreads();
        if (wid == 0) {
            bv = rv[lane]; bi = ri[lane];
#pragma unroll
            for (int off = 16; off; off >>= 1) {
                float ov = __shfl_down_sync(0xFFFFFFFFu, bv, off);
                int   oi = __shfl_down_sync(0xFFFFFFFFu, bi, off);
                if (ov > bv || (ov == bv && oi < bi)) { bv = ov; bi = oi; }
            }
            if (lane == 0) {
                idxInt[outBase + it] = bi;
                idxOutF[outBase + it] = (float)bi;
                ssx = X[bi * 3 + 0];
                ssy = X[bi * 3 + 1];
                ssz = X[bi * 3 + 2];
            }
        }
        __syncthreads();
        float sx = ssx, sy = ssy, sz = ssz;
#pragma unroll
        for (int j = 0; j < FPS_PT; j++) {
            int slot = j * 1024 + tid;
            if (slot < cnt) {
                float dx = __fsub_rn(xs[slot], sx);
                float dy = __fsub_rn(ys[slot], sy);
                float dz = __fsub_rn(zs[slot], sz);
                float d = __fadd_rn(__fadd_rn(__fmul_rn(dx, dx), __fmul_rn(dy, dy)),
                                    __fmul_rn(dz, dz));
                mind[j] = fminf(mind[j], d);
            }
        }
        __syncthreads();
    }
}

// ---------------------------------------------------------------------------
// gather sampled centroids
// ---------------------------------------------------------------------------
__global__ void gathernew_kernel(const float* __restrict__ xyz, const int* __restrict__ idxInt,
                                 float* __restrict__ newxyz, float* __restrict__ outXyz)
{
    int t = blockIdx.x * blockDim.x + threadIdx.x;   // 12288
    int d = t % 3;
    int rest = t / 3;
    int b = rest >> 10, s = rest & 1023;
    int i = idxInt[b * NPOINT + s];
    float v = xyz[((size_t)b * NPTS + i) * 3 + d];
    newxyz[t] = v;
    outXyz[t] = v;
}

// ---------------------------------------------------------------------------
// ball query: one warp per query; first 32 in-radius points in index order
// ---------------------------------------------------------------------------
__global__ void ballq_kernel(const float* __restrict__ xyz, const float* __restrict__ newxyz,
                             int* __restrict__ ballIdx)
{
    __shared__ int lists[8][32];
    int warp = threadIdx.x >> 5, lane = threadIdx.x & 31;
    int q = blockIdx.x * 8 + warp;
    int b = q >> 10;
    const float* X = xyz + (size_t)b * NPTS * 3;
    float qx = newxyz[q * 3], qy = newxyz[q * 3 + 1], qz = newxyz[q * 3 + 2];
    const float R2 = (float)(0.3 * 0.3);
    int cnt = 0;
    for (int chunk = 0; chunk < NPTS / 32; chunk++) {
        int p = chunk * 32 + lane;
        float dx = __fsub_rn(qx, X[p * 3 + 0]);
        float dy = __fsub_rn(qy, X[p * 3 + 1]);
        float dz = __fsub_rn(qz, X[p * 3 + 2]);
        float d2 = __fadd_rn(__fadd_rn(__fmul_rn(dx, dx), __fmul_rn(dy, dy)),
                             __fmul_rn(dz, dz));
        bool in = (d2 <= R2);
        unsigned m = __ballot_sync(0xFFFFFFFFu, in);
        if (m) {
            int pos = cnt + __popc(m & ((1u << lane) - 1u));
            if (in && pos < 32) lists[warp][pos] = p;
            cnt += __popc(m);
            if (cnt >= 32) break;
        }
    }
    __syncwarp();
    int c = cnt < 32 ? cnt : 32;
    int v = (lane < c) ? lists[warp][lane] : lists[warp][0];
    ballIdx[q * 32 + lane] = v;
}

// ---------------------------------------------------------------------------
// build grouped input x[131][131072]: rows 0..2 centered xyz, 3..130 features
// ---------------------------------------------------------------------------
__global__ void buildx_kernel(const float* __restrict__ xyz, const float* __restrict__ features,
                              const float* __restrict__ newxyz, const int* __restrict__ ballIdx,
                              float* __restrict__ xbuf)
{
    int col = blockIdx.x * blockDim.x + threadIdx.x;  // 131072
    int c = blockIdx.y;                               // 131
    int b = col >> 15, s = (col >> 5) & 1023;
    int idx = ballIdx[col];
    float v;
    if (c < 3)
        v = __fsub_rn(xyz[((size_t)b * NPTS + idx) * 3 + c],
                      newxyz[((b << 10) + s) * 3 + c]);
    else
        v = features[((size_t)b * CIN + (c - 3)) * NPTS + idx];
    xbuf[(size_t)c * NCOLS2D + col] = v;
}

// ---------------------------------------------------------------------------
// maxpool over nsample with layer-3 BN + relu
// ---------------------------------------------------------------------------
__global__ void maxpool_kernel(const float* __restrict__ y3, float* __restrict__ outFeat)
{
    int bs = blockIdx.x * blockDim.x + threadIdx.x;   // 4096
    int m = blockIdx.y;                               // 256
    float a = g_aff_a[3][m], c = g_aff_c[3][m];
    const float* p = y3 + (size_t)m * NCOLS2D + (size_t)bs * 32;
    float mx = -1e30f;
#pragma unroll
    for (int k = 0; k < 32; k++) mx = fmaxf(mx, fmaf(a, p[k], c));
    int b = bs >> 10, s = bs & 1023;
    outFeat[((size_t)b * 256 + m) * 1024 + s] = fmaxf(mx, 0.f);
}

// ---------------------------------------------------------------------------
// host launcher
// ---------------------------------------------------------------------------
extern "C" void kernel_launch(void* const* d_in, const int* in_sizes, int n_in,
                              void* d_out, int out_size)
{
    const float* xyz      = (const float*)d_in[0];
    const float* features = (const float*)d_in[1];
    const float* w1  = (const float*)d_in[2];
    const float* g1  = (const float*)d_in[3];
    const float* b1  = (const float*)d_in[4];
    const float* w2  = (const float*)d_in[5];
    const float* g2  = (const float*)d_in[6];
    const float* b2  = (const float*)d_in[7];
    const float* w3  = (const float*)d_in[8];
    const float* g3  = (const float*)d_in[9];
    const float* b3  = (const float*)d_in[10];
    const float* fw1 = (const float*)d_in[11];
    const float* fg1 = (const float*)d_in[12];
    const float* fb1 = (const float*)d_in[13];
    const float* fw2 = (const float*)d_in[14];
    const float* fbias2 = (const float*)d_in[15];

    float* out = (float*)d_out;
    float* outXyz    = out + OFS_XYZ;
    float* outFeat   = out + OFS_FEAT;
    float* outIdx    = out + OFS_IDX;
    float* outScores = out + OFS_SCORES;

    float* scr = nullptr;
    cudaGetSymbolAddress((void**)&scr, g_scratch);
    float* y1d    = scr + O_Y1D;
    float* xbuf   = scr + O_X;
    float* y1     = scr + O_Y1;
    float* y2     = scr + O_Y2;
    float* y3     = scr + O_Y3;
    float* margin = scr + O_MARGIN;
    float* newxyz = scr + O_NEWXYZ;
    int* fgmask   = (int*)(scr + O_FGMASK);
    int* idxInt   = (int*)(scr + O_INDICES);
    int* ballIdx  = (int*)(scr + O_BALL);
    int* fpsPid   = (int*)(scr + O_FPSPID);

    zero_stats_kernel<<<1, 256>>>();

    // 1D conv (fw1) on features
    gemm_kernel<<<dim3(NCOLS1D / GBN, 1), 256>>>(fw1, features, y1d, 64, 128, NCOLS1D, -1, 1);
    stats_kernel<<<dim3(64, 8), 256>>>(y1d, NCOLS1D, 0);
    finalize_kernel<<<1, 256>>>(64, fg1, fb1, 0, (double)NCOLS1D);

    // mask head -> scores + margin
    maskhead_kernel<<<NCOLS1D / 256, 256>>>(y1d, fw2, fbias2, outScores, margin);

    // exact top-2048 per batch
    select_kernel<<<4, 256>>>(margin, fgmask);

    // masked FPS (fg + bg), 8 instances
    cudaFuncSetAttribute(fps_kernel, cudaFuncAttributeMaxDynamicSharedMemorySize, 14336 * 3 * 4);
    fps_kernel<<<8, 1024, 14336 * 3 * 4>>>(xyz, fgmask, fpsPid, idxInt, outIdx);

    gathernew_kernel<<<12288 / 256, 256>>>(xyz, idxInt, newxyz, outXyz);
    ballq_kernel<<<NPOINT * BATCH / 8, 256>>>(xyz, newxyz, ballIdx);
    buildx_kernel<<<dim3(NCOLS2D / 256, 131), 256>>>(xyz, features, newxyz, ballIdx, xbuf);

    // conv1
    gemm_kernel<<<dim3(NCOLS2D / GBN, 1), 256>>>(w1, xbuf, y1, 128, 131, NCOLS2D, -1, 0);
    stats_kernel<<<dim3(128, 8), 256>>>(y1, NCOLS2D, 1);
    finalize_kernel<<<1, 256>>>(128, g1, b1, 1, (double)NCOLS2D);
    // conv2 (BN1+relu fused into B load)
    gemm_kernel<<<dim3(NCOLS2D / GBN, 1), 256>>>(w2, y1, y2, 128, 128, NCOLS2D, 1, 0);
    stats_kernel<<<dim3(128, 8), 256>>>(y2, NCOLS2D, 2);
    finalize_kernel<<<1, 256>>>(128, g2, b2, 2, (double)NCOLS2D);
    // conv3 (BN2+relu fused into B load)
    gemm_kernel<<<dim3(NCOLS2D / GBN, 2), 256>>>(w3, y2, y3, 256, 128, NCOLS2D, 2, 0);
    stats_kernel<<<dim3(256, 8), 256>>>(y3, NCOLS2D, 3);
    finalize_kernel<<<1, 256>>>(256, g3, b3, 3, (double)NCOLS2D);

    // BN3 + relu + maxpool over nsample
    maxpool_kernel<<<dim3(4096 / 256, 256), 256>>>(y3, outFeat);
}

// round 3
// speedup vs baseline: 1.5827x; 1.5827x over previous
#include <cuda_runtime.h>
#include <cuda_bf16.h>
#include <cstdint>
#include <cstdio>

// ---------------------------------------------------------------------------
// Problem constants
// ---------------------------------------------------------------------------
#define BATCH   4
#define NPTS    16384
#define CIN     128
#define NPOINT  1024
#define FG_NS   512
#define TOPK_K  2048
#define NSAMP   32
#define NCOLS2D (BATCH * NPOINT * NSAMP)   // 131072
#define NCOLS1D (BATCH * NPTS)             // 65536
#define KPAD    144                        // 131 padded to multiple of 16

// output layout (floats)
#define OFS_XYZ    0
#define OFS_FEAT   12288
#define OFS_IDX    (12288 + 1048576)
#define OFS_SCORES (12288 + 1048576 + 4096)

// scratch layout (floats within g_scratch)
#define O_Y1D     0ull                       // 64*65536      = 4194304
#define O_X       4194304ull                 // 144*131072    = 18874368
#define O_Y1      23068672ull                // 128*131072    = 16777216
#define O_Y2      39845888ull                // 128*131072
#define O_P3MAX   56623104ull                // 256*4096      = 1048576
#define O_P3MIN   57671680ull                // 1048576
#define O_MARGIN  58720256ull                // 65536
#define O_NEWXYZ  58785792ull                // 12288
#define O_FGMASK  58798080ull                // 65536 ints
#define O_INDICES 58863616ull                // 4096 ints
#define O_BALL    58867712ull                // 131072 ints
#define O_FPSPID  58998784ull                // 8*14336 ints
#define O_WPAD    59113472ull                // 128*144 = 18432
#define SCRATCH_FLOATS 59131904ull

__device__ float g_scratch[SCRATCH_FLOATS];

__device__ double g_sum[4][256];
__device__ double g_sumsq[4][256];
__device__ float  g_aff_a[4][256];
__device__ float  g_aff_c[4][256];

// ---------------------------------------------------------------------------
// util kernels
// ---------------------------------------------------------------------------
__global__ void zero_stats_kernel() {
    int t = threadIdx.x;
    double* s  = &g_sum[0][0];
    double* s2 = &g_sumsq[0][0];
    for (int i = t; i < 4 * 256; i += blockDim.x) { s[i] = 0.0; s2[i] = 0.0; }
}

// pad w1 [128x131] -> wpad [128x144] (cols 131..143 zero)
__global__ void padw_kernel(const float* __restrict__ w1, float* __restrict__ wpad) {
    int t = blockIdx.x * blockDim.x + threadIdx.x;   // 128*144
    int o = t / KPAD, c = t % KPAD;
    wpad[t] = (c < 131) ? w1[o * 131 + c] : 0.f;
}

// zero xbuf rows 131..143
__global__ void zeroxpad_kernel(float* __restrict__ xbuf) {
    int t = blockIdx.x * blockDim.x + threadIdx.x;   // 13*131072
    xbuf[(size_t)131 * NCOLS2D + t] = 0.f;
}

// ---------------------------------------------------------------------------
// Fused SGEMM: C[M x Ncols] = A[M x K] * B[K x Ncols]
//  - double-buffered smem, no bounds checks (dims exact multiples)
//  - bmode==1: B is features [BATCH][128][NPTS], col -> b=col>>14, n=col&16383
//  - affLayer>=0: B element -> relu(a[k]*v + c[k]) on load
//  - statsLayer>=0: per-row sum/sumsq accumulated (double atomics)
//  - poolMode==1: no C store; per (row, 32-col centroid) max/min written
// ---------------------------------------------------------------------------
template<int RT>   // rows per thread; tile TM = RT*16
__global__ void __launch_bounds__(256, 2) gemm_fused(
    const float* __restrict__ A, const float* __restrict__ B, float* __restrict__ C,
    int K, int Ncols, int affLayer, int bmode, int statsLayer, int poolMode,
    float* __restrict__ poolMax, float* __restrict__ poolMin)
{
    constexpr int TM = RT * 16;
    __shared__ float As[2][16][TM + 4];
    __shared__ float Bs[2][16][128];
    const int tid = threadIdx.x;
    const int tx = tid & 15, ty = tid >> 4;
    const int rowBase = blockIdx.y * TM;
    const int colBase = blockIdx.x * 128;

    float acc[RT][8];
#pragma unroll
    for (int i = 0; i < RT; i++)
#pragma unroll
        for (int j = 0; j < 8; j++) acc[i][j] = 0.f;

    const int ktiles = K >> 4;

    // prologue: tile 0 -> buffer 0
    {
#pragma unroll
        for (int l = 0; l < RT; l++) {
            int i = l * 256 + tid;
            int r = i >> 4, kk = i & 15;
            As[0][kk][r] = A[(rowBase + r) * K + kk];
        }
#pragma unroll
        for (int l = 0; l < 2; l++) {
            int i = l * 256 + tid;
            int kk = i >> 5, c4 = i & 31;
            int gc = colBase + c4 * 4;
            const float* src = bmode
                ? B + (((size_t)(gc >> 14) * 128 + kk) << 14) + (gc & 16383)
                : B + (size_t)kk * Ncols + gc;
            float4 v = *(const float4*)src;
            if (affLayer >= 0) {
                float a = g_aff_a[affLayer][kk], c = g_aff_c[affLayer][kk];
                v.x = fmaxf(fmaf(a, v.x, c), 0.f);
                v.y = fmaxf(fmaf(a, v.y, c), 0.f);
                v.z = fmaxf(fmaf(a, v.z, c), 0.f);
                v.w = fmaxf(fmaf(a, v.w, c), 0.f);
            }
            *(float4*)&Bs[0][kk][c4 * 4] = v;
        }
    }
    __syncthreads();

    float pa[RT];
    float4 pb0, pb1;
    for (int kt = 0; kt < ktiles; kt++) {
        const int cur = kt & 1, nxt = cur ^ 1;
        const bool more = (kt + 1 < ktiles);
        if (more) {
            const int k0 = (kt + 1) << 4;
#pragma unroll
            for (int l = 0; l < RT; l++) {
                int i = l * 256 + tid;
                int r = i >> 4, kk = i & 15;
                pa[l] = A[(rowBase + r) * K + k0 + kk];
            }
#pragma unroll
            for (int l = 0; l < 2; l++) {
                int i = l * 256 + tid;
                int kk = i >> 5, c4 = i & 31;
                int gk = k0 + kk, gc = colBase + c4 * 4;
                const float* src = bmode
                    ? B + (((size_t)(gc >> 14) * 128 + gk) << 14) + (gc & 16383)
                    : B + (size_t)gk * Ncols + gc;
                float4 v = *(const float4*)src;
                if (affLayer >= 0) {
                    float a = g_aff_a[affLayer][gk], c = g_aff_c[affLayer][gk];
                    v.x = fmaxf(fmaf(a, v.x, c), 0.f);
                    v.y = fmaxf(fmaf(a, v.y, c), 0.f);
                    v.z = fmaxf(fmaf(a, v.z, c), 0.f);
                    v.w = fmaxf(fmaf(a, v.w, c), 0.f);
                }
                if (l == 0) pb0 = v; else pb1 = v;
            }
        }
#pragma unroll
        for (int kk = 0; kk < 16; kk++) {
            float ra[RT], rb[8];
#pragma unroll
            for (int i = 0; i < RT; i++) ra[i] = As[cur][kk][ty * RT + i];
#pragma unroll
            for (int j = 0; j < 8; j++) rb[j] = Bs[cur][kk][tx * 8 + j];
#pragma unroll
            for (int i = 0; i < RT; i++)
#pragma unroll
                for (int j = 0; j < 8; j++)
                    acc[i][j] = fmaf(ra[i], rb[j], acc[i][j]);
        }
        if (more) {
#pragma unroll
            for (int l = 0; l < RT; l++) {
                int i = l * 256 + tid;
                int r = i >> 4, kk = i & 15;
                As[nxt][kk][r] = pa[l];
            }
            {
                int kk = tid >> 5, c4 = tid & 31;
                *(float4*)&Bs[nxt][kk][c4 * 4] = pb0;
            }
            {
                int i = 256 + tid;
                int kk = i >> 5, c4 = i & 31;
                *(float4*)&Bs[nxt][kk][c4 * 4] = pb1;
            }
        }
        __syncthreads();
    }

    // ---- epilogue ----
    if (poolMode == 0) {
#pragma unroll
        for (int i = 0; i < RT; i++) {
            float* dst = C + (size_t)(rowBase + ty * RT + i) * Ncols + colBase + tx * 8;
            *(float4*)dst       = make_float4(acc[i][0], acc[i][1], acc[i][2], acc[i][3]);
            *(float4*)(dst + 4) = make_float4(acc[i][4], acc[i][5], acc[i][6], acc[i][7]);
        }
    } else {
#pragma unroll
        for (int i = 0; i < RT; i++) {
            float mx = acc[i][0], mn = acc[i][0];
#pragma unroll
            for (int j = 1; j < 8; j++) { mx = fmaxf(mx, acc[i][j]); mn = fminf(mn, acc[i][j]); }
            mx = fmaxf(mx, __shfl_xor_sync(0xFFFFFFFFu, mx, 1));
            mn = fminf(mn, __shfl_xor_sync(0xFFFFFFFFu, mn, 1));
            mx = fmaxf(mx, __shfl_xor_sync(0xFFFFFFFFu, mx, 2));
            mn = fminf(mn, __shfl_xor_sync(0xFFFFFFFFu, mn, 2));
            if ((tx & 3) == 0) {
                int cent = (colBase >> 5) + (tx >> 2);
                int gr = rowBase + ty * RT + i;
                poolMax[gr * 4096 + cent] = mx;
                poolMin[gr * 4096 + cent] = mn;
            }
        }
    }
    if (statsLayer >= 0) {
#pragma unroll
        for (int i = 0; i < RT; i++) {
            float s = 0.f, s2 = 0.f;
#pragma unroll
            for (int j = 0; j < 8; j++) { float v = acc[i][j]; s += v; s2 = fmaf(v, v, s2); }
#pragma unroll
            for (int off = 1; off < 16; off <<= 1) {
                s  += __shfl_xor_sync(0xFFFFFFFFu, s, off);
                s2 += __shfl_xor_sync(0xFFFFFFFFu, s2, off);
            }
            if (tx == 0) {
                int gr = rowBase + ty * RT + i;
                atomicAdd(&g_sum[statsLayer][gr], (double)s);
                atomicAdd(&g_sumsq[statsLayer][gr], (double)s2);
            }
        }
    }
}

__global__ void finalize_kernel(int M, const float* __restrict__ g,
                                const float* __restrict__ beta, int layer, double cnt)
{
    int m = threadIdx.x;
    if (m < M) {
        double mu = g_sum[layer][m] / cnt;
        double var = g_sumsq[layer][m] / cnt - mu * mu;
        float a = g[m] * rsqrtf((float)var + 1e-5f);
        g_aff_a[layer][m] = a;
        g_aff_c[layer][m] = beta[m] - (float)mu * a;
    }
}

// ---------------------------------------------------------------------------
// mask head: scores + margin  (reads raw y1d, applies layer-0 BN+relu)
// ---------------------------------------------------------------------------
__global__ void maskhead_kernel(const float* __restrict__ y1d,
                                const float* __restrict__ fw2,
                                const float* __restrict__ fbias2,
                                float* __restrict__ outScores,
                                float* __restrict__ margin)
{
    int col = blockIdx.x * blockDim.x + threadIdx.x;   // 65536
    int b = col >> 14, n = col & 16383;
    float s0 = fbias2[0], s1 = fbias2[1];
#pragma unroll 4
    for (int c = 0; c < 64; c++) {
        float a = g_aff_a[0][c], cc = g_aff_c[0][c];
        float v = fmaxf(fmaf(a, y1d[(size_t)c * NCOLS1D + col], cc), 0.f);
        s0 = fmaf(fw2[c], v, s0);
        s1 = fmaf(fw2[64 + c], v, s1);
    }
    outScores[b * 32768 + n]         = s0;
    outScores[b * 32768 + 16384 + n] = s1;
    float mx = fmaxf(s0, s1);
    float e0 = expf(s0 - mx), e1 = expf(s1 - mx);
    margin[col] = (e1 - e0) / (e0 + e1);
}

// ---------------------------------------------------------------------------
// exact top-2048 selection via 64-bit radix select (value desc, index asc)
// ---------------------------------------------------------------------------
__device__ __forceinline__ unsigned long long makeKey(float f, int i)
{
    unsigned u = __float_as_uint(f);
    u = (u & 0x80000000u) ? ~u : (u | 0x80000000u);
    return ((unsigned long long)u << 32) | (unsigned)(0xFFFFFFFFu - (unsigned)i);
}

__global__ void select_kernel(const float* __restrict__ margin, int* __restrict__ fgmask)
{
    __shared__ unsigned hist[256];
    __shared__ unsigned long long sprefix;
    __shared__ int skrem;
    int b = blockIdx.x, tid = threadIdx.x;
    const float* M = margin + b * NPTS;
    if (tid == 0) { sprefix = 0ull; skrem = TOPK_K; }
    __syncthreads();
    for (int pos = 56; pos >= 0; pos -= 8) {
        hist[tid] = 0;
        __syncthreads();
        unsigned long long pref = sprefix;
        for (int i = tid; i < NPTS; i += 256) {
            unsigned long long key = makeKey(M[i], i);
            bool act = (pos == 56) || ((key >> (pos + 8)) == (pref >> (pos + 8)));
            if (act) atomicAdd(&hist[(unsigned)(key >> pos) & 255u], 1u);
        }
        __syncthreads();
        if (tid == 0) {
            int k = skrem;
            int v = 255;
            while (v > 0 && (int)hist[v] < k) { k -= (int)hist[v]; v--; }
            skrem = k;
            sprefix = pref | ((unsigned long long)(unsigned)v << pos);
        }
        __syncthreads();
    }
    unsigned long long kth = sprefix;
    for (int i = tid; i < NPTS; i += 256)
        fgmask[b * NPTS + i] = (makeKey(M[i], i) >= kth) ? 1 : 0;
}

// ---------------------------------------------------------------------------
// masked FPS: 8 CTAs (batch x {fg,bg}); coords in SMEM (float2 + float),
// mind/pid in registers, argmax fused into the update pass. Exact counts
// (2048 fg / 14336 bg) -> guard-free fully-unrolled loops.
// rn intrinsics (no fma) match reference arithmetic; ties -> smallest index.
// ---------------------------------------------------------------------------
template<int J>
__device__ __forceinline__ void fps_body(
    const float2* __restrict__ xy, const float* __restrict__ zs,
    const int* __restrict__ pidbuf, const float* __restrict__ X,
    int outBase, int* __restrict__ idxInt, float* __restrict__ idxOutF,
    float* rv, int* ri, float* swin)
{
    int tid = threadIdx.x;
    int lane = tid & 31, wid = tid >> 5;

    float mind[J];
    int pid[J];
#pragma unroll
    for (int j = 0; j < J; j++) { mind[j] = 1e10f; pid[j] = pidbuf[j * 1024 + tid]; }

    // initial argmax: all mind equal -> smallest pid
    float bv = 1e10f;
    int bi = pid[0];
#pragma unroll
    for (int j = 1; j < J; j++) bi = min(bi, pid[j]);

    for (int it = 0; it < FG_NS; it++) {
        // two-level reduce of (bv, bi)
#pragma unroll
        for (int off = 16; off; off >>= 1) {
            float ov = __shfl_down_sync(0xFFFFFFFFu, bv, off);
            int   oi = __shfl_down_sync(0xFFFFFFFFu, bi, off);
            if (ov > bv || (ov == bv && oi < bi)) { bv = ov; bi = oi; }
        }
        if (lane == 0) { rv[wid] = bv; ri[wid] = bi; }
        __syncthreads();
        if (wid == 0) {
            bv = rv[lane]; bi = ri[lane];
#pragma unroll
            for (int off = 16; off; off >>= 1) {
                float ov = __shfl_down_sync(0xFFFFFFFFu, bv, off);
                int   oi = __shfl_down_sync(0xFFFFFFFFu, bi, off);
                if (ov > bv || (ov == bv && oi < bi)) { bv = ov; bi = oi; }
            }
            if (lane == 0) {
                idxInt[outBase + it] = bi;
                idxOutF[outBase + it] = (float)bi;
                swin[0] = X[bi * 3 + 0];
                swin[1] = X[bi * 3 + 1];
                swin[2] = X[bi * 3 + 2];
            }
        }
        __syncthreads();
        float sx = swin[0], sy = swin[1], sz = swin[2];
        bv = -4.f; bi = 0x7FFFFFFF;
#pragma unroll
        for (int j = 0; j < J; j++) {
            float2 p = xy[j * 1024 + tid];
            float pz = zs[j * 1024 + tid];
            float dx = __fsub_rn(p.x, sx);
            float dy = __fsub_rn(p.y, sy);
            float dz = __fsub_rn(pz, sz);
            float d = __fadd_rn(__fadd_rn(__fmul_rn(dx, dx), __fmul_rn(dy, dy)),
                                __fmul_rn(dz, dz));
            float m = fminf(mind[j], d);
            mind[j] = m;
            if (m > bv || (m == bv && pid[j] < bi)) { bv = m; bi = pid[j]; }
        }
    }
}

__global__ void __launch_bounds__(1024, 1) fps_kernel(
    const float* __restrict__ xyz, const int* __restrict__ fgmask,
    int* __restrict__ fpsPid, int* __restrict__ idxInt, float* __restrict__ idxOutF)
{
    extern __shared__ float sh[];
    float2* xy = (float2*)sh;             // 14336 float2
    float* zs = sh + 2 * 14336;           // 14336 float
    __shared__ int scnt;
    __shared__ float rv[32];
    __shared__ int ri[32];
    __shared__ float swin[3];

    int blk = blockIdx.x;
    int b = blk >> 1;
    int isFg = !(blk & 1);
    const float* X = xyz + (size_t)b * NPTS * 3;
    const int* Mk = fgmask + b * NPTS;
    int* pidbuf = fpsPid + blk * 14336;
    int tid = threadIdx.x;

    if (tid == 0) scnt = 0;
    __syncthreads();
    for (int i = tid; i < NPTS; i += 1024) {
        int m = Mk[i];
        if (!isFg) m = !m;
        if (m) {
            int pos = atomicAdd(&scnt, 1);
            xy[pos] = make_float2(X[i * 3 + 0], X[i * 3 + 1]);
            zs[pos] = X[i * 3 + 2];
            pidbuf[pos] = i;
        }
    }
    __syncthreads();

    int outBase = b * NPOINT + (isFg ? 0 : FG_NS);
    if (isFg)
        fps_body<2>(xy, zs, pidbuf, X, outBase, idxInt, idxOutF, rv, ri, swin);
    else
        fps_body<14>(xy, zs, pidbuf, X, outBase, idxInt, idxOutF, rv, ri, swin);
}

// ---------------------------------------------------------------------------
// gather sampled centroids
// ---------------------------------------------------------------------------
__global__ void gathernew_kernel(const float* __restrict__ xyz, const int* __restrict__ idxInt,
                                 float* __restrict__ newxyz, float* __restrict__ outXyz)
{
    int t = blockIdx.x * blockDim.x + threadIdx.x;   // 12288
    int d = t % 3;
    int rest = t / 3;
    int b = rest >> 10, s = rest & 1023;
    int i = idxInt[b * NPOINT + s];
    float v = xyz[((size_t)b * NPTS + i) * 3 + d];
    newxyz[t] = v;
    outXyz[t] = v;
}

// ---------------------------------------------------------------------------
// ball query: one warp per query; first 32 in-radius points in index order
// ---------------------------------------------------------------------------
__global__ void ballq_kernel(const float* __restrict__ xyz, const float* __restrict__ newxyz,
                             int* __restrict__ ballIdx)
{
    __shared__ int lists[8][32];
    int warp = threadIdx.x >> 5, lane = threadIdx.x & 31;
    int q = blockIdx.x * 8 + warp;
    int b = q >> 10;
    const float* X = xyz + (size_t)b * NPTS * 3;
    float qx = newxyz[q * 3], qy = newxyz[q * 3 + 1], qz = newxyz[q * 3 + 2];
    const float R2 = (float)(0.3 * 0.3);
    int cnt = 0;
    for (int chunk = 0; chunk < NPTS / 32; chunk++) {
        int p = chunk * 32 + lane;
        float dx = __fsub_rn(qx, X[p * 3 + 0]);
        float dy = __fsub_rn(qy, X[p * 3 + 1]);
        float dz = __fsub_rn(qz, X[p * 3 + 2]);
        float d2 = __fadd_rn(__fadd_rn(__fmul_rn(dx, dx), __fmul_rn(dy, dy)),
                             __fmul_rn(dz, dz));
        bool in = (d2 <= R2);
        unsigned m = __ballot_sync(0xFFFFFFFFu, in);
        if (m) {
            int pos = cnt + __popc(m & ((1u << lane) - 1u));
            if (in && pos < 32) lists[warp][pos] = p;
            cnt += __popc(m);
            if (cnt >= 32) break;
        }
    }
    __syncwarp();
    int c = cnt < 32 ? cnt : 32;
    int v = (lane < c) ? lists[warp][lane] : lists[warp][0];
    ballIdx[q * 32 + lane] = v;
}

// ---------------------------------------------------------------------------
// build grouped input x[144][131072]: rows 0..2 centered xyz, 3..130 features
// ---------------------------------------------------------------------------
__global__ void buildx_kernel(const float* __restrict__ xyz, const float* __restrict__ features,
                              const float* __restrict__ newxyz, const int* __restrict__ ballIdx,
                              float* __restrict__ xbuf)
{
    int col = blockIdx.x * blockDim.x + threadIdx.x;  // 131072
    int c = blockIdx.y;                               // 131
    int b = col >> 15, s = (col >> 5) & 1023;
    int idx = ballIdx[col];
    float v;
    if (c < 3)
        v = __fsub_rn(xyz[((size_t)b * NPTS + idx) * 3 + c],
                      newxyz[((b << 10) + s) * 3 + c]);
    else
        v = features[((size_t)b * CIN + (c - 3)) * NPTS + idx];
    xbuf[(size_t)c * NCOLS2D + col] = v;
}

// ---------------------------------------------------------------------------
// final maxpool: pick max (a>=0) or min (a<0) of raw y3, apply BN3 + relu
// ---------------------------------------------------------------------------
__global__ void maxpool_final(const float* __restrict__ pmax, const float* __restrict__ pmin,
                              float* __restrict__ outFeat)
{
    int t = blockIdx.x * blockDim.x + threadIdx.x;   // 1048576
    int m = t >> 12;
    int cent = t & 4095;
    float a = g_aff_a[3][m], c = g_aff_c[3][m];
    float y = (a >= 0.f) ? pmax[t] : pmin[t];
    float v = fmaxf(fmaf(a, y, c), 0.f);
    int b = cent >> 10, s = cent & 1023;
    outFeat[(((size_t)b * 256 + m) << 10) + s] = v;
}

// ---------------------------------------------------------------------------
// host launcher
// ---------------------------------------------------------------------------
extern "C" void kernel_launch(void* const* d_in, const int* in_sizes, int n_in,
                              void* d_out, int out_size)
{
    const float* xyz      = (const float*)d_in[0];
    const float* features = (const float*)d_in[1];
    const float* w1  = (const float*)d_in[2];
    const float* g1  = (const float*)d_in[3];
    const float* b1  = (const float*)d_in[4];
    const float* w2  = (const float*)d_in[5];
    const float* g2  = (const float*)d_in[6];
    const float* b2  = (const float*)d_in[7];
    const float* w3  = (const float*)d_in[8];
    const float* g3  = (const float*)d_in[9];
    const float* b3  = (const float*)d_in[10];
    const float* fw1 = (const float*)d_in[11];
    const float* fg1 = (const float*)d_in[12];
    const float* fb1 = (const float*)d_in[13];
    const float* fw2 = (const float*)d_in[14];
    const float* fbias2 = (const float*)d_in[15];

    float* out = (float*)d_out;
    float* outXyz    = out + OFS_XYZ;
    float* outFeat   = out + OFS_FEAT;
    float* outIdx    = out + OFS_IDX;
    float* outScores = out + OFS_SCORES;

    float* scr = nullptr;
    cudaGetSymbolAddress((void**)&scr, g_scratch);
    float* y1d    = scr + O_Y1D;
    float* xbuf   = scr + O_X;
    float* y1     = scr + O_Y1;
    float* y2     = scr + O_Y2;
    float* p3max  = scr + O_P3MAX;
    float* p3min  = scr + O_P3MIN;
    float* margin = scr + O_MARGIN;
    float* newxyz = scr + O_NEWXYZ;
    float* wpad   = scr + O_WPAD;
    int* fgmask   = (int*)(scr + O_FGMASK);
    int* idxInt   = (int*)(scr + O_INDICES);
    int* ballIdx  = (int*)(scr + O_BALL);
    int* fpsPid   = (int*)(scr + O_FPSPID);

    zero_stats_kernel<<<1, 256>>>();
    padw_kernel<<<(128 * KPAD) / 256, 256>>>(w1, wpad);

    // 1D conv (fw1, M=64, K=128) on features; stats fused (layer 0)
    gemm_fused<4><<<dim3(NCOLS1D / 128, 1), 256>>>(
        fw1, features, y1d, 128, NCOLS1D, -1, 1, 0, 0, nullptr, nullptr);
    finalize_kernel<<<1, 256>>>(64, fg1, fb1, 0, (double)NCOLS1D);

    maskhead_kernel<<<NCOLS1D / 256, 256>>>(y1d, fw2, fbias2, outScores, margin);
    select_kernel<<<4, 256>>>(margin, fgmask);

    cudaFuncSetAttribute(fps_kernel, cudaFuncAttributeMaxDynamicSharedMemorySize, 14336 * 3 * 4);
    fps_kernel<<<8, 1024, 14336 * 3 * 4>>>(xyz, fgmask, fpsPid, idxInt, outIdx);

    gathernew_kernel<<<12288 / 256, 256>>>(xyz, idxInt, newxyz, outXyz);
    ballq_kernel<<<NPOINT * BATCH / 8, 256>>>(xyz, newxyz, ballIdx);
    zeroxpad_kernel<<<(13 * NCOLS2D) / 256, 256>>>(xbuf);
    buildx_kernel<<<dim3(NCOLS2D / 256, 131), 256>>>(xyz, features, newxyz, ballIdx, xbuf);

    // conv1 (K padded to 144), stats fused (layer 1)
    gemm_fused<8><<<dim3(NCOLS2D / 128, 1), 256>>>(
        wpad, xbuf, y1, KPAD, NCOLS2D, -1, 0, 1, 0, nullptr, nullptr);
    finalize_kernel<<<1, 256>>>(128, g1, b1, 1, (double)NCOLS2D);

    // conv2 (BN1+relu fused into B load), stats fused (layer 2)
    gemm_fused<8><<<dim3(NCOLS2D / 128, 1), 256>>>(
        w2, y1, y2, 128, NCOLS2D, 1, 0, 2, 0, nullptr, nullptr);
    finalize_kernel<<<1, 256>>>(128, g2, b2, 2, (double)NCOLS2D);

    // conv3 (BN2+relu fused into B load), stats + centroid max/min pool fused
    gemm_fused<8><<<dim3(NCOLS2D / 128, 2), 256>>>(
        w3, y2, nullptr, 128, NCOLS2D, 2, 0, 3, 1, p3max, p3min);
    finalize_kernel<<<1, 256>>>(256, g3, b3, 3, (double)NCOLS2D);

    maxpool_final<<<(256 * 4096) / 256, 256>>>(p3max, p3min, outFeat);
}

// round 5
// speedup vs baseline: 1.6473x; 1.0409x over previous
#include <cuda_runtime.h>
#include <cuda_bf16.h>
#include <cstdint>
#include <cstdio>

// ---------------------------------------------------------------------------
// Problem constants
// ---------------------------------------------------------------------------
#define BATCH   4
#define NPTS    16384
#define CIN     128
#define NPOINT  1024
#define FG_NS   512
#define TOPK_K  2048
#define NSAMP   32
#define NCOLS2D (BATCH * NPOINT * NSAMP)   // 131072
#define NCOLS1D (BATCH * NPTS)             // 65536
#define KX1     160                        // conv1 K (131) padded to 160

// output layout (floats)
#define OFS_XYZ    0
#define OFS_FEAT   12288
#define OFS_IDX    (12288 + 1048576)
#define OFS_SCORES (12288 + 1048576 + 4096)

// scratch layout (floats within g_scratch)
#define O_Y1D     0ull                       // 64*65536      = 4194304
#define O_XT      4194304ull                 // 131072*160    = 20971520
#define O_Y1T     25165824ull                // 131072*128    = 16777216
#define O_Y2T     41943040ull                // 16777216
#define O_P3MAX   58720256ull                // 256*4096 = 1048576
#define O_P3MIN   59768832ull                // 1048576
#define O_MARGIN  60817408ull                // 65536
#define O_NEWXYZ  60882944ull                // 12288
#define O_FGMASK  60895232ull                // 65536 ints
#define O_INDICES 60960768ull                // 4096 ints
#define O_BALL    60964864ull                // 131072 ints
#define O_FPSPID  61095936ull                // 8*14336 ints
#define O_WPAD    61210624ull                // 256*160 = 40960 (max)
#define SCRATCH_FLOATS 61251584ull

__device__ float g_scratch[SCRATCH_FLOATS];

__device__ double g_sum[4][256];
__device__ double g_sumsq[4][256];
__device__ float  g_aff_a[4][256];
__device__ float  g_aff_c[4][256];

// ---------------------------------------------------------------------------
// mma.sync tf32 helpers (baseline PTX, works on compute_103 target)
// ---------------------------------------------------------------------------
__device__ __forceinline__ float tf32r(float x) {
    uint32_t u;
    asm("cvt.rna.tf32.f32 %0, %1;" : "=r"(u) : "f"(x));
    return __uint_as_float(u);
}
__device__ __forceinline__ void mma_tf32(float* c, uint32_t a0, uint32_t a1,
                                         uint32_t a2, uint32_t a3,
                                         uint32_t b0, uint32_t b1) {
    asm("mma.sync.aligned.m16n8k8.row.col.f32.tf32.tf32.f32 "
        "{%0,%1,%2,%3},{%4,%5,%6,%7},{%8,%9},{%0,%1,%2,%3};"
        : "+f"(c[0]), "+f"(c[1]), "+f"(c[2]), "+f"(c[3])
        : "r"(a0), "r"(a1), "r"(a2), "r"(a3), "r"(b0), "r"(b1));
}

// ---------------------------------------------------------------------------
// util kernels
// ---------------------------------------------------------------------------
__global__ void zero_stats_kernel() {
    int t = threadIdx.x;
    double* s  = &g_sum[0][0];
    double* s2 = &g_sumsq[0][0];
    for (int i = t; i < 4 * 256; i += blockDim.x) { s[i] = 0.0; s2[i] = 0.0; }
}

// pad w1 [128x131] -> wpad [128x160]
__global__ void padw_kernel(const float* __restrict__ w1, float* __restrict__ wpad) {
    int t = blockIdx.x * blockDim.x + threadIdx.x;   // 128*160
    int o = t / KX1, c = t % KX1;
    wpad[t] = (c < 131) ? w1[o * 131 + c] : 0.f;
}

// ---------------------------------------------------------------------------
// tf32 mma.sync conv GEMM.
//   CTA tile: 128 rows (W outputs) x 128 cols (points). 8 warps = 2x4,
//   warp tile 64x32, m16n8k8 atoms (4x4 per warp per k-step).
//   A = W [M][KE] K-major; B = Xin [col][KE] (transposed activations).
//   AFF>=0: BN+relu applied to B on load. STATS: row sums fused.
//   POOL=0: Yout[col][row] transposed store (SMEM-staged, coalesced).
//   POOL=1: per-row max/min over each 32-col centroid group (no Yout).
// ---------------------------------------------------------------------------
template<int KE, int AFF, int STATS, int POOL>
__global__ void __launch_bounds__(256, 1) conv_mma(
    const float* __restrict__ W, const float* __restrict__ Xin,
    float* __restrict__ Yout, float* __restrict__ poolMax, float* __restrict__ poolMin)
{
    constexpr int LDK = KE + 4;
    extern __shared__ float sm[];
    float* As = sm;                  // [128][LDK]
    float* Bs = sm + 128 * LDK;      // [128][LDK]
    const int tid = threadIdx.x;
    const int wid = tid >> 5, lane = tid & 31;
    const int g = lane >> 2, t = lane & 3;
    const int wm = wid >> 2, wn = wid & 3;
    const int rowBase = blockIdx.y * 128;
    const int colBase = blockIdx.x * 128;

    // load & cvt A (weights)
    for (int i = tid; i < 128 * (KE / 4); i += 256) {
        int r = i / (KE / 4), k = (i % (KE / 4)) * 4;
        float4 v = *(const float4*)(W + (size_t)(rowBase + r) * KE + k);
        As[r * LDK + k + 0] = tf32r(v.x);
        As[r * LDK + k + 1] = tf32r(v.y);
        As[r * LDK + k + 2] = tf32r(v.z);
        As[r * LDK + k + 3] = tf32r(v.w);
    }
    // load & cvt B (activations), optional BN+relu
    for (int i = tid; i < 128 * (KE / 4); i += 256) {
        int r = i / (KE / 4), k = (i % (KE / 4)) * 4;
        float4 v = *(const float4*)(Xin + (size_t)(colBase + r) * KE + k);
        if (AFF >= 0) {
            float4 av = *(const float4*)&g_aff_a[AFF][k];
            float4 cv = *(const float4*)&g_aff_c[AFF][k];
            v.x = fmaxf(fmaf(av.x, v.x, cv.x), 0.f);
            v.y = fmaxf(fmaf(av.y, v.y, cv.y), 0.f);
            v.z = fmaxf(fmaf(av.z, v.z, cv.z), 0.f);
            v.w = fmaxf(fmaf(av.w, v.w, cv.w), 0.f);
        }
        Bs[r * LDK + k + 0] = tf32r(v.x);
        Bs[r * LDK + k + 1] = tf32r(v.y);
        Bs[r * LDK + k + 2] = tf32r(v.z);
        Bs[r * LDK + k + 3] = tf32r(v.w);
    }
    __syncthreads();

    float acc[4][4][4];
#pragma unroll
    for (int i = 0; i < 4; i++)
#pragma unroll
        for (int j = 0; j < 4; j++)
#pragma unroll
            for (int c = 0; c < 4; c++) acc[i][j][c] = 0.f;

    const float* Arow0 = As + (size_t)(wm * 64 + g) * LDK + t;       // +ma*16*LDK
    const float* Arow8 = Arow0 + 8 * LDK;
    const float* Bcol0 = Bs + (size_t)(wn * 32 + g) * LDK + t;       // +nb*8*LDK

#pragma unroll 4
    for (int ks = 0; ks < KE / 8; ks++) {
        const int k0 = ks * 8;
        uint32_t a[4][4], b[4][2];
#pragma unroll
        for (int ma = 0; ma < 4; ma++) {
            const float* p0 = Arow0 + ma * 16 * LDK + k0;
            const float* p8 = Arow8 + ma * 16 * LDK + k0;
            a[ma][0] = __float_as_uint(p0[0]);
            a[ma][1] = __float_as_uint(p8[0]);
            a[ma][2] = __float_as_uint(p0[4]);
            a[ma][3] = __float_as_uint(p8[4]);
        }
#pragma unroll
        for (int nb = 0; nb < 4; nb++) {
            const float* pb = Bcol0 + nb * 8 * LDK + k0;
            b[nb][0] = __float_as_uint(pb[0]);
            b[nb][1] = __float_as_uint(pb[4]);
        }
#pragma unroll
        for (int ma = 0; ma < 4; ma++)
#pragma unroll
            for (int nb = 0; nb < 4; nb++)
                mma_tf32(acc[ma][nb], a[ma][0], a[ma][1], a[ma][2], a[ma][3],
                         b[nb][0], b[nb][1]);
    }

    // ---- fused stats (+ optional pool) from registers ----
    // c0=C[g][2t], c1=C[g][2t+1], c2=C[g+8][2t], c3=C[g+8][2t+1]
#pragma unroll
    for (int ma = 0; ma < 4; ma++) {
        int r0 = wm * 64 + ma * 16 + g;
        float s0 = 0.f, q0 = 0.f, s1 = 0.f, q1 = 0.f;
        float mx0 = -1e30f, mn0 = 1e30f, mx1 = -1e30f, mn1 = 1e30f;
#pragma unroll
        for (int nb = 0; nb < 4; nb++) {
            float c0 = acc[ma][nb][0], c1 = acc[ma][nb][1];
            float c2 = acc[ma][nb][2], c3 = acc[ma][nb][3];
            s0 += c0 + c1; q0 = fmaf(c0, c0, fmaf(c1, c1, q0));
            s1 += c2 + c3; q1 = fmaf(c2, c2, fmaf(c3, c3, q1));
            if (POOL) {
                mx0 = fmaxf(mx0, fmaxf(c0, c1)); mn0 = fminf(mn0, fminf(c0, c1));
                mx1 = fmaxf(mx1, fmaxf(c2, c3)); mn1 = fminf(mn1, fminf(c2, c3));
            }
        }
#pragma unroll
        for (int off = 1; off < 4; off <<= 1) {
            s0 += __shfl_xor_sync(0xFFFFFFFFu, s0, off);
            q0 += __shfl_xor_sync(0xFFFFFFFFu, q0, off);
            s1 += __shfl_xor_sync(0xFFFFFFFFu, s1, off);
            q1 += __shfl_xor_sync(0xFFFFFFFFu, q1, off);
            if (POOL) {
                mx0 = fmaxf(mx0, __shfl_xor_sync(0xFFFFFFFFu, mx0, off));
                mn0 = fminf(mn0, __shfl_xor_sync(0xFFFFFFFFu, mn0, off));
                mx1 = fmaxf(mx1, __shfl_xor_sync(0xFFFFFFFFu, mx1, off));
                mn1 = fminf(mn1, __shfl_xor_sync(0xFFFFFFFFu, mn1, off));
            }
        }
        if (t == 0) {
            atomicAdd(&g_sum[STATS][rowBase + r0], (double)s0);
            atomicAdd(&g_sumsq[STATS][rowBase + r0], (double)q0);
            atomicAdd(&g_sum[STATS][rowBase + r0 + 8], (double)s1);
            atomicAdd(&g_sumsq[STATS][rowBase + r0 + 8], (double)q1);
            if (POOL) {
                int cent = (colBase >> 5) + wn;
                poolMax[(size_t)(rowBase + r0) * 4096 + cent] = mx0;
                poolMin[(size_t)(rowBase + r0) * 4096 + cent] = mn0;
                poolMax[(size_t)(rowBase + r0 + 8) * 4096 + cent] = mx1;
                poolMin[(size_t)(rowBase + r0 + 8) * 4096 + cent] = mn1;
            }
        }
    }

    // ---- transposed Yout store via SMEM staging ----
    if (!POOL) {
        __syncthreads();               // done reading As/Bs
        float* Ct = As;                // [128 cols][132]
#pragma unroll
        for (int ma = 0; ma < 4; ma++) {
            int r0 = wm * 64 + ma * 16 + g;
#pragma unroll
            for (int nb = 0; nb < 4; nb++) {
                int col0 = wn * 32 + nb * 8 + 2 * t;
                Ct[col0 * 132 + r0]           = acc[ma][nb][0];
                Ct[(col0 + 1) * 132 + r0]     = acc[ma][nb][1];
                Ct[col0 * 132 + r0 + 8]       = acc[ma][nb][2];
                Ct[(col0 + 1) * 132 + r0 + 8] = acc[ma][nb][3];
            }
        }
        __syncthreads();
        for (int i = tid; i < 128 * 32; i += 256) {
            int col = i >> 5;
            int r4 = (i & 31) * 4;
            float4 v = *(float4*)&Ct[col * 132 + r4];
            *(float4*)(Yout + (size_t)(colBase + col) * 128 + r4) = v;
        }
    }
}

// ---------------------------------------------------------------------------
// SIMT SGEMM (fp32-exact mask-head conv), double buffered
// ---------------------------------------------------------------------------
template<int RT>
__global__ void __launch_bounds__(256, 2) gemm_fused(
    const float* __restrict__ A, const float* __restrict__ B, float* __restrict__ C,
    int K, int Ncols, int affLayer, int bmode, int statsLayer)
{
    constexpr int TM = RT * 16;
    __shared__ float As[2][16][TM + 4];
    __shared__ float Bs[2][16][128];
    const int tid = threadIdx.x;
    const int tx = tid & 15, ty = tid >> 4;
    const int rowBase = blockIdx.y * TM;
    const int colBase = blockIdx.x * 128;

    float acc[RT][8];
#pragma unroll
    for (int i = 0; i < RT; i++)
#pragma unroll
        for (int j = 0; j < 8; j++) acc[i][j] = 0.f;

    const int ktiles = K >> 4;
    {
#pragma unroll
        for (int l = 0; l < RT; l++) {
            int i = l * 256 + tid;
            int r = i >> 4, kk = i & 15;
            As[0][kk][r] = A[(rowBase + r) * K + kk];
        }
#pragma unroll
        for (int l = 0; l < 2; l++) {
            int i = l * 256 + tid;
            int kk = i >> 5, c4 = i & 31;
            int gc = colBase + c4 * 4;
            const float* src = bmode
                ? B + (((size_t)(gc >> 14) * 128 + kk) << 14) + (gc & 16383)
                : B + (size_t)kk * Ncols + gc;
            float4 v = *(const float4*)src;
            *(float4*)&Bs[0][kk][c4 * 4] = v;
        }
    }
    __syncthreads();

    float pa[RT];
    float4 pb0, pb1;
    for (int kt = 0; kt < ktiles; kt++) {
        const int cur = kt & 1, nxt = cur ^ 1;
        const bool more = (kt + 1 < ktiles);
        if (more) {
            const int k0 = (kt + 1) << 4;
#pragma unroll
            for (int l = 0; l < RT; l++) {
                int i = l * 256 + tid;
                int r = i >> 4, kk = i & 15;
                pa[l] = A[(rowBase + r) * K + k0 + kk];
            }
#pragma unroll
            for (int l = 0; l < 2; l++) {
                int i = l * 256 + tid;
                int kk = i >> 5, c4 = i & 31;
                int gk = k0 + kk, gc = colBase + c4 * 4;
                const float* src = bmode
                    ? B + (((size_t)(gc >> 14) * 128 + gk) << 14) + (gc & 16383)
                    : B + (size_t)gk * Ncols + gc;
                float4 v = *(const float4*)src;
                if (l == 0) pb0 = v; else pb1 = v;
            }
        }
#pragma unroll
        for (int kk = 0; kk < 16; kk++) {
            float ra[RT], rb[8];
#pragma unroll
            for (int i = 0; i < RT; i++) ra[i] = As[cur][kk][ty * RT + i];
#pragma unroll
            for (int j = 0; j < 8; j++) rb[j] = Bs[cur][kk][tx * 8 + j];
#pragma unroll
            for (int i = 0; i < RT; i++)
#pragma unroll
                for (int j = 0; j < 8; j++)
                    acc[i][j] = fmaf(ra[i], rb[j], acc[i][j]);
        }
        if (more) {
#pragma unroll
            for (int l = 0; l < RT; l++) {
                int i = l * 256 + tid;
                int r = i >> 4, kk = i & 15;
                As[nxt][kk][r] = pa[l];
            }
            { int kk = tid >> 5, c4 = tid & 31; *(float4*)&Bs[nxt][kk][c4 * 4] = pb0; }
            { int i = 256 + tid; int kk = i >> 5, c4 = i & 31; *(float4*)&Bs[nxt][kk][c4 * 4] = pb1; }
        }
        __syncthreads();
    }
#pragma unroll
    for (int i = 0; i < RT; i++) {
        float* dst = C + (size_t)(rowBase + ty * RT + i) * Ncols + colBase + tx * 8;
        *(float4*)dst       = make_float4(acc[i][0], acc[i][1], acc[i][2], acc[i][3]);
        *(float4*)(dst + 4) = make_float4(acc[i][4], acc[i][5], acc[i][6], acc[i][7]);
    }
    if (statsLayer >= 0) {
#pragma unroll
        for (int i = 0; i < RT; i++) {
            float s = 0.f, s2 = 0.f;
#pragma unroll
            for (int j = 0; j < 8; j++) { float v = acc[i][j]; s += v; s2 = fmaf(v, v, s2); }
#pragma unroll
            for (int off = 1; off < 16; off <<= 1) {
                s  += __shfl_xor_sync(0xFFFFFFFFu, s, off);
                s2 += __shfl_xor_sync(0xFFFFFFFFu, s2, off);
            }
            if (tx == 0) {
                int gr = rowBase + ty * RT + i;
                atomicAdd(&g_sum[statsLayer][gr], (double)s);
                atomicAdd(&g_sumsq[statsLayer][gr], (double)s2);
            }
        }
    }
}

__global__ void finalize_kernel(int M, const float* __restrict__ g,
                                const float* __restrict__ beta, int layer, double cnt)
{
    int m = threadIdx.x;
    if (m < M) {
        double mu = g_sum[layer][m] / cnt;
        double var = g_sumsq[layer][m] / cnt - mu * mu;
        float a = g[m] * rsqrtf((float)var + 1e-5f);
        g_aff_a[layer][m] = a;
        g_aff_c[layer][m] = beta[m] - (float)mu * a;
    }
}

// ---------------------------------------------------------------------------
// mask head: scores + margin  (reads raw y1d, applies layer-0 BN+relu)
// ---------------------------------------------------------------------------
__global__ void maskhead_kernel(const float* __restrict__ y1d,
                                const float* __restrict__ fw2,
                                const float* __restrict__ fbias2,
                                float* __restrict__ outScores,
                                float* __restrict__ margin)
{
    int col = blockIdx.x * blockDim.x + threadIdx.x;   // 65536
    int b = col >> 14, n = col & 16383;
    float s0 = fbias2[0], s1 = fbias2[1];
#pragma unroll 4
    for (int c = 0; c < 64; c++) {
        float a = g_aff_a[0][c], cc = g_aff_c[0][c];
        float v = fmaxf(fmaf(a, y1d[(size_t)c * NCOLS1D + col], cc), 0.f);
        s0 = fmaf(fw2[c], v, s0);
        s1 = fmaf(fw2[64 + c], v, s1);
    }
    outScores[b * 32768 + n]         = s0;
    outScores[b * 32768 + 16384 + n] = s1;
    float mx = fmaxf(s0, s1);
    float e0 = expf(s0 - mx), e1 = expf(s1 - mx);
    margin[col] = (e1 - e0) / (e0 + e1);
}

// ---------------------------------------------------------------------------
// exact top-2048 selection via 64-bit radix select (value desc, index asc)
// ---------------------------------------------------------------------------
__device__ __forceinline__ unsigned long long makeKey(float f, int i)
{
    unsigned u = __float_as_uint(f);
    u = (u & 0x80000000u) ? ~u : (u | 0x80000000u);
    return ((unsigned long long)u << 32) | (unsigned)(0xFFFFFFFFu - (unsigned)i);
}

__global__ void select_kernel(const float* __restrict__ margin, int* __restrict__ fgmask)
{
    __shared__ unsigned hist[256];
    __shared__ unsigned long long sprefix;
    __shared__ int skrem;
    int b = blockIdx.x, tid = threadIdx.x;
    const float* M = margin + b * NPTS;
    if (tid == 0) { sprefix = 0ull; skrem = TOPK_K; }
    __syncthreads();
    for (int pos = 56; pos >= 0; pos -= 8) {
        hist[tid] = 0;
        __syncthreads();
        unsigned long long pref = sprefix;
        for (int i = tid; i < NPTS; i += 256) {
            unsigned long long key = makeKey(M[i], i);
            bool act = (pos == 56) || ((key >> (pos + 8)) == (pref >> (pos + 8)));
            if (act) atomicAdd(&hist[(unsigned)(key >> pos) & 255u], 1u);
        }
        __syncthreads();
        if (tid == 0) {
            int k = skrem;
            int v = 255;
            while (v > 0 && (int)hist[v] < k) { k -= (int)hist[v]; v--; }
            skrem = k;
            sprefix = pref | ((unsigned long long)(unsigned)v << pos);
        }
        __syncthreads();
    }
    unsigned long long kth = sprefix;
    for (int i = tid; i < NPTS; i += 256)
        fgmask[b * NPTS + i] = (makeKey(M[i], i) >= kth) ? 1 : 0;
}

// ---------------------------------------------------------------------------
// masked FPS (unchanged from round 3)
// ---------------------------------------------------------------------------
template<int J>
__device__ __forceinline__ void fps_body(
    const float2* __restrict__ xy, const float* __restrict__ zs,
    const int* __restrict__ pidbuf, const float* __restrict__ X,
    int outBase, int* __restrict__ idxInt, float* __restrict__ idxOutF,
    float* rv, int* ri, float* swin)
{
    int tid = threadIdx.x;
    int lane = tid & 31, wid = tid >> 5;

    float mind[J];
    int pid[J];
#pragma unroll
    for (int j = 0; j < J; j++) { mind[j] = 1e10f; pid[j] = pidbuf[j * 1024 + tid]; }

    float bv = 1e10f;
    int bi = pid[0];
#pragma unroll
    for (int j = 1; j < J; j++) bi = min(bi, pid[j]);

    for (int it = 0; it < FG_NS; it++) {
#pragma unroll
        for (int off = 16; off; off >>= 1) {
            float ov = __shfl_down_sync(0xFFFFFFFFu, bv, off);
            int   oi = __shfl_down_sync(0xFFFFFFFFu, bi, off);
            if (ov > bv || (ov == bv && oi < bi)) { bv = ov; bi = oi; }
        }
        if (lane == 0) { rv[wid] = bv; ri[wid] = bi; }
        __syncthreads();
        if (wid == 0) {
            bv = rv[lane]; bi = ri[lane];
#pragma unroll
            for (int off = 16; off; off >>= 1) {
                float ov = __shfl_down_sync(0xFFFFFFFFu, bv, off);
                int   oi = __shfl_down_sync(0xFFFFFFFFu, bi, off);
                if (ov > bv || (ov == bv && oi < bi)) { bv = ov; bi = oi; }
            }
            if (lane == 0) {
                idxInt[outBase + it] = bi;
                idxOutF[outBase + it] = (float)bi;
                swin[0] = X[bi * 3 + 0];
                swin[1] = X[bi * 3 + 1];
                swin[2] = X[bi * 3 + 2];
            }
        }
        __syncthreads();
        float sx = swin[0], sy = swin[1], sz = swin[2];
        bv = -4.f; bi = 0x7FFFFFFF;
#pragma unroll
        for (int j = 0; j < J; j++) {
            float2 p = xy[j * 1024 + tid];
            float pz = zs[j * 1024 + tid];
            float dx = __fsub_rn(p.x, sx);
            float dy = __fsub_rn(p.y, sy);
            float dz = __fsub_rn(pz, sz);
            float d = __fadd_rn(__fadd_rn(__fmul_rn(dx, dx), __fmul_rn(dy, dy)),
                                __fmul_rn(dz, dz));
            float m = fminf(mind[j], d);
            mind[j] = m;
            if (m > bv || (m == bv && pid[j] < bi)) { bv = m; bi = pid[j]; }
        }
    }
}

__global__ void __launch_bounds__(1024, 1) fps_kernel(
    const float* __restrict__ xyz, const int* __restrict__ fgmask,
    int* __restrict__ fpsPid, int* __restrict__ idxInt, float* __restrict__ idxOutF)
{
    extern __shared__ float sh[];
    float2* xy = (float2*)sh;
    float* zs = sh + 2 * 14336;
    __shared__ int scnt;
    __shared__ float rv[32];
    __shared__ int ri[32];
    __shared__ float swin[3];

    int blk = blockIdx.x;
    int b = blk >> 1;
    int isFg = !(blk & 1);
    const float* X = xyz + (size_t)b * NPTS * 3;
    const int* Mk = fgmask + b * NPTS;
    int* pidbuf = fpsPid + blk * 14336;
    int tid = threadIdx.x;

    if (tid == 0) scnt = 0;
    __syncthreads();
    for (int i = tid; i < NPTS; i += 1024) {
        int m = Mk[i];
        if (!isFg) m = !m;
        if (m) {
            int pos = atomicAdd(&scnt, 1);
            xy[pos] = make_float2(X[i * 3 + 0], X[i * 3 + 1]);
            zs[pos] = X[i * 3 + 2];
            pidbuf[pos] = i;
        }
    }
    __syncthreads();

    int outBase = b * NPOINT + (isFg ? 0 : FG_NS);
    if (isFg)
        fps_body<2>(xy, zs, pidbuf, X, outBase, idxInt, idxOutF, rv, ri, swin);
    else
        fps_body<14>(xy, zs, pidbuf, X, outBase, idxInt, idxOutF, rv, ri, swin);
}

// ---------------------------------------------------------------------------
// gather sampled centroids
// ---------------------------------------------------------------------------
__global__ void gathernew_kernel(const float* __restrict__ xyz, const int* __restrict__ idxInt,
                                 float* __restrict__ newxyz, float* __restrict__ outXyz)
{
    int t = blockIdx.x * blockDim.x + threadIdx.x;   // 12288
    int d = t % 3;
    int rest = t / 3;
    int b = rest >> 10, s = rest & 1023;
    int i = idxInt[b * NPOINT + s];
    float v = xyz[((size_t)b * NPTS + i) * 3 + d];
    newxyz[t] = v;
    outXyz[t] = v;
}

// ---------------------------------------------------------------------------
// ball query: one warp per query
// ---------------------------------------------------------------------------
__global__ void ballq_kernel(const float* __restrict__ xyz, const float* __restrict__ newxyz,
                             int* __restrict__ ballIdx)
{
    __shared__ int lists[8][32];
    int warp = threadIdx.x >> 5, lane = threadIdx.x & 31;
    int q = blockIdx.x * 8 + warp;
    int b = q >> 10;
    const float* X = xyz + (size_t)b * NPTS * 3;
    float qx = newxyz[q * 3], qy = newxyz[q * 3 + 1], qz = newxyz[q * 3 + 2];
    const float R2 = (float)(0.3 * 0.3);
    int cnt = 0;
    for (int chunk = 0; chunk < NPTS / 32; chunk++) {
        int p = chunk * 32 + lane;
        float dx = __fsub_rn(qx, X[p * 3 + 0]);
        float dy = __fsub_rn(qy, X[p * 3 + 1]);
        float dz = __fsub_rn(qz, X[p * 3 + 2]);
        float d2 = __fadd_rn(__fadd_rn(__fmul_rn(dx, dx), __fmul_rn(dy, dy)),
                             __fmul_rn(dz, dz));
        bool in = (d2 <= R2);
        unsigned m = __ballot_sync(0xFFFFFFFFu, in);
        if (m) {
            int pos = cnt + __popc(m & ((1u << lane) - 1u));
            if (in && pos < 32) lists[warp][pos] = p;
            cnt += __popc(m);
            if (cnt >= 32) break;
        }
    }
    __syncwarp();
    int c = cnt < 32 ? cnt : 32;
    int v = (lane < c) ? lists[warp][lane] : lists[warp][0];
    ballIdx[q * 32 + lane] = v;
}

// ---------------------------------------------------------------------------
// build transposed grouped input xbufT[131072][160]
// ---------------------------------------------------------------------------
__global__ void buildxT_kernel(const float* __restrict__ xyz, const float* __restrict__ features,
                               const float* __restrict__ newxyz, const int* __restrict__ ballIdx,
                               float* __restrict__ xbufT)
{
    int t = blockIdx.x * blockDim.x + threadIdx.x;  // 131072*160
    int c = t % KX1;
    int col = t / KX1;
    float v = 0.f;
    if (c < 131) {
        int b = col >> 15, s = (col >> 5) & 1023;
        int idx = ballIdx[col];
        if (c < 3)
            v = __fsub_rn(xyz[((size_t)b * NPTS + idx) * 3 + c],
                          newxyz[((b << 10) + s) * 3 + c]);
        else
            v = features[((size_t)b * CIN + (c - 3)) * NPTS + idx];
    }
    xbufT[t] = v;
}

// ---------------------------------------------------------------------------
// final maxpool: pick max (a>=0) or min (a<0) of raw y3, apply BN3 + relu
// ---------------------------------------------------------------------------
__global__ void maxpool_final(const float* __restrict__ pmax, const float* __restrict__ pmin,
                              float* __restrict__ outFeat)
{
    int t = blockIdx.x * blockDim.x + threadIdx.x;   // 1048576
    int m = t >> 12;
    int cent = t & 4095;
    float a = g_aff_a[3][m], c = g_aff_c[3][m];
    float y = (a >= 0.f) ? pmax[t] : pmin[t];
    float v = fmaxf(fmaf(a, y, c), 0.f);
    int b = cent >> 10, s = cent & 1023;
    outFeat[(((size_t)b * 256 + m) << 10) + s] = v;
}

// ---------------------------------------------------------------------------
// host launcher
// ---------------------------------------------------------------------------
extern "C" void kernel_launch(void* const* d_in, const int* in_sizes, int n_in,
                              void* d_out, int out_size)
{
    const float* xyz      = (const float*)d_in[0];
    const float* features = (const float*)d_in[1];
    const float* w1  = (const float*)d_in[2];
    const float* g1  = (const float*)d_in[3];
    const float* b1  = (const float*)d_in[4];
    const float* w2  = (const float*)d_in[5];
    const float* g2  = (const float*)d_in[6];
    const float* b2  = (const float*)d_in[7];
    const float* w3  = (const float*)d_in[8];
    const float* g3  = (const float*)d_in[9];
    const float* b3  = (const float*)d_in[10];
    const float* fw1 = (const float*)d_in[11];
    const float* fg1 = (const float*)d_in[12];
    const float* fb1 = (const float*)d_in[13];
    const float* fw2 = (const float*)d_in[14];
    const float* fbias2 = (const float*)d_in[15];

    float* out = (float*)d_out;
    float* outXyz    = out + OFS_XYZ;
    float* outFeat   = out + OFS_FEAT;
    float* outIdx    = out + OFS_IDX;
    float* outScores = out + OFS_SCORES;

    float* scr = nullptr;
    cudaGetSymbolAddress((void**)&scr, g_scratch);
    float* y1d    = scr + O_Y1D;
    float* xbufT  = scr + O_XT;
    float* y1T    = scr + O_Y1T;
    float* y2T    = scr + O_Y2T;
    float* p3max  = scr + O_P3MAX;
    float* p3min  = scr + O_P3MIN;
    float* margin = scr + O_MARGIN;
    float* newxyz = scr + O_NEWXYZ;
    float* wpad   = scr + O_WPAD;
    int* fgmask   = (int*)(scr + O_FGMASK);
    int* idxInt   = (int*)(scr + O_INDICES);
    int* ballIdx  = (int*)(scr + O_BALL);
    int* fpsPid   = (int*)(scr + O_FPSPID);

    zero_stats_kernel<<<1, 256>>>();
    padw_kernel<<<(128 * KX1) / 256, 256>>>(w1, wpad);

    // mask-head conv (fp32 exact, M=64, K=128); stats fused (layer 0)
    gemm_fused<4><<<dim3(NCOLS1D / 128, 1), 256>>>(
        fw1, features, y1d, 128, NCOLS1D, -1, 1, 0);
    finalize_kernel<<<1, 256>>>(64, fg1, fb1, 0, (double)NCOLS1D);

    maskhead_kernel<<<NCOLS1D / 256, 256>>>(y1d, fw2, fbias2, outScores, margin);
    select_kernel<<<4, 256>>>(margin, fgmask);

    cudaFuncSetAttribute(fps_kernel, cudaFuncAttributeMaxDynamicSharedMemorySize, 14336 * 3 * 4);
    fps_kernel<<<8, 1024, 14336 * 3 * 4>>>(xyz, fgmask, fpsPid, idxInt, outIdx);

    gathernew_kernel<<<12288 / 256, 256>>>(xyz, idxInt, newxyz, outXyz);
    ballq_kernel<<<NPOINT * BATCH / 8, 256>>>(xyz, newxyz, ballIdx);
    buildxT_kernel<<<(NCOLS2D * KX1) / 256, 256>>>(xyz, features, newxyz, ballIdx, xbufT);

    // conv1: tf32 mma.sync, K=160(padded); stats layer 1
    {
        auto k = conv_mma<KX1, -1, 1, 0>;
        size_t sm = (size_t)2 * 128 * (KX1 + 4) * 4;
        cudaFuncSetAttribute(k, cudaFuncAttributeMaxDynamicSharedMemorySize, (int)sm);
        k<<<dim3(NCOLS2D / 128, 1), 256, sm>>>(wpad, xbufT, y1T, nullptr, nullptr);
    }
    finalize_kernel<<<1, 256>>>(128, g1, b1, 1, (double)NCOLS2D);

    // conv2: BN1+relu on B-load; stats layer 2
    {
        auto k = conv_mma<128, 1, 2, 0>;
        size_t sm = (size_t)2 * 128 * 132 * 4;
        cudaFuncSetAttribute(k, cudaFuncAttributeMaxDynamicSharedMemorySize, (int)sm);
        k<<<dim3(NCOLS2D / 128, 1), 256, sm>>>(w2, y1T, y2T, nullptr, nullptr);
    }
    finalize_kernel<<<1, 256>>>(128, g2, b2, 2, (double)NCOLS2D);

    // conv3: M=256 via grid.y=2, BN2+relu on B-load; stats layer 3 + pool
    {
        auto k = conv_mma<128, 2, 3, 1>;
        size_t sm = (size_t)2 * 128 * 132 * 4;
        cudaFuncSetAttribute(k, cudaFuncAttributeMaxDynamicSharedMemorySize, (int)sm);
        k<<<dim3(NCOLS2D / 128, 2), 256, sm>>>(w3, y2T, nullptr, p3max, p3min);
    }
    finalize_kernel<<<1, 256>>>(256, g3, b3, 3, (double)NCOLS2D);

    maxpool_final<<<(256 * 4096) / 256, 256>>>(p3max, p3min, outFeat);
}

// round 6
// speedup vs baseline: 1.6521x; 1.0029x over previous
#include <cuda_runtime.h>
#include <cuda_bf16.h>
#include <cstdint>
#include <cstdio>

// ---------------------------------------------------------------------------
// Problem constants
// ---------------------------------------------------------------------------
#define BATCH   4
#define NPTS    16384
#define CIN     128
#define NPOINT  1024
#define FG_NS   512
#define TOPK_K  2048
#define NSAMP   32
#define NCOLS2D (BATCH * NPOINT * NSAMP)   // 131072
#define NCOLS1D (BATCH * NPTS)             // 65536
#define KX1     160                        // conv1 K (131) padded to 160

// output layout (floats)
#define OFS_XYZ    0
#define OFS_FEAT   12288
#define OFS_IDX    (12288 + 1048576)
#define OFS_SCORES (12288 + 1048576 + 4096)

// scratch layout (floats within g_scratch)
#define O_Y1D     0ull                       // 64*65536      = 4194304
#define O_XT      4194304ull                 // 131072*160    = 20971520
#define O_Y1T     25165824ull                // 131072*128    = 16777216
#define O_Y2T     41943040ull                // 16777216
#define O_P3MAX   58720256ull                // 256*4096 = 1048576
#define O_P3MIN   59768832ull                // 1048576
#define O_MARGIN  60817408ull                // 65536
#define O_NEWXYZ  60882944ull                // 12288
#define O_FGMASK  60895232ull                // 65536 ints
#define O_INDICES 60960768ull                // 4096 ints
#define O_BALL    60964864ull                // 131072 ints
#define O_FPSPID  61095936ull                // 8*14336 ints
#define O_WPAD    61210624ull                // 256*160 = 40960 (max)
#define SCRATCH_FLOATS 61251584ull

__device__ float g_scratch[SCRATCH_FLOATS];

__device__ double g_sum[4][256];
__device__ double g_sumsq[4][256];
__device__ float  g_aff_a[4][256];
__device__ float  g_aff_c[4][256];

// ---------------------------------------------------------------------------
// mma.sync tf32 helpers (baseline PTX, works on compute_103 target)
// ---------------------------------------------------------------------------
__device__ __forceinline__ float tf32r(float x) {
    uint32_t u;
    asm("cvt.rna.tf32.f32 %0, %1;" : "=r"(u) : "f"(x));
    return __uint_as_float(u);
}
__device__ __forceinline__ void mma_tf32(float* c, uint32_t a0, uint32_t a1,
                                         uint32_t a2, uint32_t a3,
                                         uint32_t b0, uint32_t b1) {
    asm("mma.sync.aligned.m16n8k8.row.col.f32.tf32.tf32.f32 "
        "{%0,%1,%2,%3},{%4,%5,%6,%7},{%8,%9},{%0,%1,%2,%3};"
        : "+f"(c[0]), "+f"(c[1]), "+f"(c[2]), "+f"(c[3])
        : "r"(a0), "r"(a1), "r"(a2), "r"(a3), "r"(b0), "r"(b1));
}

// ---------------------------------------------------------------------------
// util kernels
// ---------------------------------------------------------------------------
__global__ void zero_stats_kernel() {
    int t = threadIdx.x;
    double* s  = &g_sum[0][0];
    double* s2 = &g_sumsq[0][0];
    for (int i = t; i < 4 * 256; i += blockDim.x) { s[i] = 0.0; s2[i] = 0.0; }
}

// pad w1 [128x131] -> wpad [128x160]
__global__ void padw_kernel(const float* __restrict__ w1, float* __restrict__ wpad) {
    int t = blockIdx.x * blockDim.x + threadIdx.x;   // 128*160
    int o = t / KX1, c = t % KX1;
    wpad[t] = (c < 131) ? w1[o * 131 + c] : 0.f;
}

// ---------------------------------------------------------------------------
// tf32 mma.sync conv GEMM.
//   CTA tile: 128 rows (W outputs) x 128 cols (points). 8 warps = 2x4,
//   warp tile 64x32, m16n8k8 atoms (4x4 per warp per k-step).
//   A = W [M][KE] K-major; B = Xin [col][KE] (transposed activations).
//   AFF>=0: BN+relu applied to B on load. STATS: row sums fused.
//   POOL=0: Yout[col][row] transposed store (SMEM-staged, coalesced).
//   POOL=1: per-row max/min over each 32-col centroid group (no Yout).
// ---------------------------------------------------------------------------
template<int KE, int AFF, int STATS, int POOL>
__global__ void __launch_bounds__(256, 1) conv_mma(
    const float* __restrict__ W, const float* __restrict__ Xin,
    float* __restrict__ Yout, float* __restrict__ poolMax, float* __restrict__ poolMin)
{
    constexpr int LDK = KE + 4;
    extern __shared__ float sm[];
    float* As = sm;                  // [128][LDK]
    float* Bs = sm + 128 * LDK;      // [128][LDK]
    const int tid = threadIdx.x;
    const int wid = tid >> 5, lane = tid & 31;
    const int g = lane >> 2, t = lane & 3;
    const int wm = wid >> 2, wn = wid & 3;
    const int rowBase = blockIdx.y * 128;
    const int colBase = blockIdx.x * 128;

    // load & cvt A (weights)
    for (int i = tid; i < 128 * (KE / 4); i += 256) {
        int r = i / (KE / 4), k = (i % (KE / 4)) * 4;
        float4 v = *(const float4*)(W + (size_t)(rowBase + r) * KE + k);
        As[r * LDK + k + 0] = tf32r(v.x);
        As[r * LDK + k + 1] = tf32r(v.y);
        As[r * LDK + k + 2] = tf32r(v.z);
        As[r * LDK + k + 3] = tf32r(v.w);
    }
    // load & cvt B (activations), optional BN+relu
    for (int i = tid; i < 128 * (KE / 4); i += 256) {
        int r = i / (KE / 4), k = (i % (KE / 4)) * 4;
        float4 v = *(const float4*)(Xin + (size_t)(colBase + r) * KE + k);
        if (AFF >= 0) {
            float4 av = *(const float4*)&g_aff_a[AFF][k];
            float4 cv = *(const float4*)&g_aff_c[AFF][k];
            v.x = fmaxf(fmaf(av.x, v.x, cv.x), 0.f);
            v.y = fmaxf(fmaf(av.y, v.y, cv.y), 0.f);
            v.z = fmaxf(fmaf(av.z, v.z, cv.z), 0.f);
            v.w = fmaxf(fmaf(av.w, v.w, cv.w), 0.f);
        }
        Bs[r * LDK + k + 0] = tf32r(v.x);
        Bs[r * LDK + k + 1] = tf32r(v.y);
        Bs[r * LDK + k + 2] = tf32r(v.z);
        Bs[r * LDK + k + 3] = tf32r(v.w);
    }
    __syncthreads();

    float acc[4][4][4];
#pragma unroll
    for (int i = 0; i < 4; i++)
#pragma unroll
        for (int j = 0; j < 4; j++)
#pragma unroll
            for (int c = 0; c < 4; c++) acc[i][j][c] = 0.f;

    const float* Arow0 = As + (size_t)(wm * 64 + g) * LDK + t;       // +ma*16*LDK
    const float* Arow8 = Arow0 + 8 * LDK;
    const float* Bcol0 = Bs + (size_t)(wn * 32 + g) * LDK + t;       // +nb*8*LDK

#pragma unroll 4
    for (int ks = 0; ks < KE / 8; ks++) {
        const int k0 = ks * 8;
        uint32_t a[4][4], b[4][2];
#pragma unroll
        for (int ma = 0; ma < 4; ma++) {
            const float* p0 = Arow0 + ma * 16 * LDK + k0;
            const float* p8 = Arow8 + ma * 16 * LDK + k0;
            a[ma][0] = __float_as_uint(p0[0]);
            a[ma][1] = __float_as_uint(p8[0]);
            a[ma][2] = __float_as_uint(p0[4]);
            a[ma][3] = __float_as_uint(p8[4]);
        }
#pragma unroll
        for (int nb = 0; nb < 4; nb++) {
            const float* pb = Bcol0 + nb * 8 * LDK + k0;
            b[nb][0] = __float_as_uint(pb[0]);
            b[nb][1] = __float_as_uint(pb[4]);
        }
#pragma unroll
        for (int ma = 0; ma < 4; ma++)
#pragma unroll
            for (int nb = 0; nb < 4; nb++)
                mma_tf32(acc[ma][nb], a[ma][0], a[ma][1], a[ma][2], a[ma][3],
                         b[nb][0], b[nb][1]);
    }

    // ---- fused stats (+ optional pool) from registers ----
    // c0=C[g][2t], c1=C[g][2t+1], c2=C[g+8][2t], c3=C[g+8][2t+1]
#pragma unroll
    for (int ma = 0; ma < 4; ma++) {
        int r0 = wm * 64 + ma * 16 + g;
        float s0 = 0.f, q0 = 0.f, s1 = 0.f, q1 = 0.f;
        float mx0 = -1e30f, mn0 = 1e30f, mx1 = -1e30f, mn1 = 1e30f;
#pragma unroll
        for (int nb = 0; nb < 4; nb++) {
            float c0 = acc[ma][nb][0], c1 = acc[ma][nb][1];
            float c2 = acc[ma][nb][2], c3 = acc[ma][nb][3];
            s0 += c0 + c1; q0 = fmaf(c0, c0, fmaf(c1, c1, q0));
            s1 += c2 + c3; q1 = fmaf(c2, c2, fmaf(c3, c3, q1));
            if (POOL) {
                mx0 = fmaxf(mx0, fmaxf(c0, c1)); mn0 = fminf(mn0, fminf(c0, c1));
                mx1 = fmaxf(mx1, fmaxf(c2, c3)); mn1 = fminf(mn1, fminf(c2, c3));
            }
        }
#pragma unroll
        for (int off = 1; off < 4; off <<= 1) {
            s0 += __shfl_xor_sync(0xFFFFFFFFu, s0, off);
            q0 += __shfl_xor_sync(0xFFFFFFFFu, q0, off);
            s1 += __shfl_xor_sync(0xFFFFFFFFu, s1, off);
            q1 += __shfl_xor_sync(0xFFFFFFFFu, q1, off);
            if (POOL) {
                mx0 = fmaxf(mx0, __shfl_xor_sync(0xFFFFFFFFu, mx0, off));
                mn0 = fminf(mn0, __shfl_xor_sync(0xFFFFFFFFu, mn0, off));
                mx1 = fmaxf(mx1, __shfl_xor_sync(0xFFFFFFFFu, mx1, off));
                mn1 = fminf(mn1, __shfl_xor_sync(0xFFFFFFFFu, mn1, off));
            }
        }
        if (t == 0) {
            atomicAdd(&g_sum[STATS][rowBase + r0], (double)s0);
            atomicAdd(&g_sumsq[STATS][rowBase + r0], (double)q0);
            atomicAdd(&g_sum[STATS][rowBase + r0 + 8], (double)s1);
            atomicAdd(&g_sumsq[STATS][rowBase + r0 + 8], (double)q1);
            if (POOL) {
                int cent = (colBase >> 5) + wn;
                poolMax[(size_t)(rowBase + r0) * 4096 + cent] = mx0;
                poolMin[(size_t)(rowBase + r0) * 4096 + cent] = mn0;
                poolMax[(size_t)(rowBase + r0 + 8) * 4096 + cent] = mx1;
                poolMin[(size_t)(rowBase + r0 + 8) * 4096 + cent] = mn1;
            }
        }
    }

    // ---- transposed Yout store via SMEM staging ----
    if (!POOL) {
        __syncthreads();               // done reading As/Bs
        float* Ct = As;                // [128 cols][132]
#pragma unroll
        for (int ma = 0; ma < 4; ma++) {
            int r0 = wm * 64 + ma * 16 + g;
#pragma unroll
            for (int nb = 0; nb < 4; nb++) {
                int col0 = wn * 32 + nb * 8 + 2 * t;
                Ct[col0 * 132 + r0]           = acc[ma][nb][0];
                Ct[(col0 + 1) * 132 + r0]     = acc[ma][nb][1];
                Ct[col0 * 132 + r0 + 8]       = acc[ma][nb][2];
                Ct[(col0 + 1) * 132 + r0 + 8] = acc[ma][nb][3];
            }
        }
        __syncthreads();
        for (int i = tid; i < 128 * 32; i += 256) {
            int col = i >> 5;
            int r4 = (i & 31) * 4;
            float4 v = *(float4*)&Ct[col * 132 + r4];
            *(float4*)(Yout + (size_t)(colBase + col) * 128 + r4) = v;
        }
    }
}

// ---------------------------------------------------------------------------
// SIMT SGEMM (fp32-exact mask-head conv), double buffered
// ---------------------------------------------------------------------------
template<int RT>
__global__ void __launch_bounds__(256, 2) gemm_fused(
    const float* __restrict__ A, const float* __restrict__ B, float* __restrict__ C,
    int K, int Ncols, int affLayer, int bmode, int statsLayer)
{
    constexpr int TM = RT * 16;
    __shared__ float As[2][16][TM + 4];
    __shared__ float Bs[2][16][128];
    const int tid = threadIdx.x;
    const int tx = tid & 15, ty = tid >> 4;
    const int rowBase = blockIdx.y * TM;
    const int colBase = blockIdx.x * 128;

    float acc[RT][8];
#pragma unroll
    for (int i = 0; i < RT; i++)
#pragma unroll
        for (int j = 0; j < 8; j++) acc[i][j] = 0.f;

    const int ktiles = K >> 4;
    {
#pragma unroll
        for (int l = 0; l < RT; l++) {
            int i = l * 256 + tid;
            int r = i >> 4, kk = i & 15;
            As[0][kk][r] = A[(rowBase + r) * K + kk];
        }
#pragma unroll
        for (int l = 0; l < 2; l++) {
            int i = l * 256 + tid;
            int kk = i >> 5, c4 = i & 31;
            int gc = colBase + c4 * 4;
            const float* src = bmode
                ? B + (((size_t)(gc >> 14) * 128 + kk) << 14) + (gc & 16383)
                : B + (size_t)kk * Ncols + gc;
            float4 v = *(const float4*)src;
            *(float4*)&Bs[0][kk][c4 * 4] = v;
        }
    }
    __syncthreads();

    float pa[RT];
    float4 pb0, pb1;
    for (int kt = 0; kt < ktiles; kt++) {
        const int cur = kt & 1, nxt = cur ^ 1;
        const bool more = (kt + 1 < ktiles);
        if (more) {
            const int k0 = (kt + 1) << 4;
#pragma unroll
            for (int l = 0; l < RT; l++) {
                int i = l * 256 + tid;
                int r = i >> 4, kk = i & 15;
                pa[l] = A[(rowBase + r) * K + k0 + kk];
            }
#pragma unroll
            for (int l = 0; l < 2; l++) {
                int i = l * 256 + tid;
                int kk = i >> 5, c4 = i & 31;
                int gk = k0 + kk, gc = colBase + c4 * 4;
                const float* src = bmode
                    ? B + (((size_t)(gc >> 14) * 128 + gk) << 14) + (gc & 16383)
                    : B + (size_t)gk * Ncols + gc;
                float4 v = *(const float4*)src;
                if (l == 0) pb0 = v; else pb1 = v;
            }
        }
#pragma unroll
        for (int kk = 0; kk < 16; kk++) {
            float ra[RT], rb[8];
#pragma unroll
            for (int i = 0; i < RT; i++) ra[i] = As[cur][kk][ty * RT + i];
#pragma unroll
            for (int j = 0; j < 8; j++) rb[j] = Bs[cur][kk][tx * 8 + j];
#pragma unroll
            for (int i = 0; i < RT; i++)
#pragma unroll
                for (int j = 0; j < 8; j++)
                    acc[i][j] = fmaf(ra[i], rb[j], acc[i][j]);
        }
        if (more) {
#pragma unroll
            for (int l = 0; l < RT; l++) {
                int i = l * 256 + tid;
                int r = i >> 4, kk = i & 15;
                As[nxt][kk][r] = pa[l];
            }
            { int kk = tid >> 5, c4 = tid & 31; *(float4*)&Bs[nxt][kk][c4 * 4] = pb0; }
            { int i = 256 + tid; int kk = i >> 5, c4 = i & 31; *(float4*)&Bs[nxt][kk][c4 * 4] = pb1; }
        }
        __syncthreads();
    }
#pragma unroll
    for (int i = 0; i < RT; i++) {
        float* dst = C + (size_t)(rowBase + ty * RT + i) * Ncols + colBase + tx * 8;
        *(float4*)dst       = make_float4(acc[i][0], acc[i][1], acc[i][2], acc[i][3]);
        *(float4*)(dst + 4) = make_float4(acc[i][4], acc[i][5], acc[i][6], acc[i][7]);
    }
    if (statsLayer >= 0) {
#pragma unroll
        for (int i = 0; i < RT; i++) {
            float s = 0.f, s2 = 0.f;
#pragma unroll
            for (int j = 0; j < 8; j++) { float v = acc[i][j]; s += v; s2 = fmaf(v, v, s2); }
#pragma unroll
            for (int off = 1; off < 16; off <<= 1) {
                s  += __shfl_xor_sync(0xFFFFFFFFu, s, off);
                s2 += __shfl_xor_sync(0xFFFFFFFFu, s2, off);
            }
            if (tx == 0) {
                int gr = rowBase + ty * RT + i;
                atomicAdd(&g_sum[statsLayer][gr], (double)s);
                atomicAdd(&g_sumsq[statsLayer][gr], (double)s2);
            }
        }
    }
}

__global__ void finalize_kernel(int M, const float* __restrict__ g,
                                const float* __restrict__ beta, int layer, double cnt)
{
    int m = threadIdx.x;
    if (m < M) {
        double mu = g_sum[layer][m] / cnt;
        double var = g_sumsq[layer][m] / cnt - mu * mu;
        float a = g[m] * rsqrtf((float)var + 1e-5f);
        g_aff_a[layer][m] = a;
        g_aff_c[layer][m] = beta[m] - (float)mu * a;
    }
}

// ---------------------------------------------------------------------------
// mask head: scores + margin  (reads raw y1d, applies layer-0 BN+relu)
// ---------------------------------------------------------------------------
__global__ void maskhead_kernel(const float* __restrict__ y1d,
                                const float* __restrict__ fw2,
                                const float* __restrict__ fbias2,
                                float* __restrict__ outScores,
                                float* __restrict__ margin)
{
    int col = blockIdx.x * blockDim.x + threadIdx.x;   // 65536
    int b = col >> 14, n = col & 16383;
    float s0 = fbias2[0], s1 = fbias2[1];
#pragma unroll 4
    for (int c = 0; c < 64; c++) {
        float a = g_aff_a[0][c], cc = g_aff_c[0][c];
        float v = fmaxf(fmaf(a, y1d[(size_t)c * NCOLS1D + col], cc), 0.f);
        s0 = fmaf(fw2[c], v, s0);
        s1 = fmaf(fw2[64 + c], v, s1);
    }
    outScores[b * 32768 + n]         = s0;
    outScores[b * 32768 + 16384 + n] = s1;
    float mx = fmaxf(s0, s1);
    float e0 = expf(s0 - mx), e1 = expf(s1 - mx);
    margin[col] = (e1 - e0) / (e0 + e1);
}

// ---------------------------------------------------------------------------
// exact top-2048 selection via 64-bit radix select (value desc, index asc)
// ---------------------------------------------------------------------------
__device__ __forceinline__ unsigned long long makeKey(float f, int i)
{
    unsigned u = __float_as_uint(f);
    u = (u & 0x80000000u) ? ~u : (u | 0x80000000u);
    return ((unsigned long long)u << 32) | (unsigned)(0xFFFFFFFFu - (unsigned)i);
}

__global__ void select_kernel(const float* __restrict__ margin, int* __restrict__ fgmask)
{
    __shared__ unsigned hist[256];
    __shared__ unsigned long long sprefix;
    __shared__ int skrem;
    int b = blockIdx.x, tid = threadIdx.x;
    const float* M = margin + b * NPTS;
    if (tid == 0) { sprefix = 0ull; skrem = TOPK_K; }
    __syncthreads();
    for (int pos = 56; pos >= 0; pos -= 8) {
        hist[tid] = 0;
        __syncthreads();
        unsigned long long pref = sprefix;
        for (int i = tid; i < NPTS; i += 256) {
            unsigned long long key = makeKey(M[i], i);
            bool act = (pos == 56) || ((key >> (pos + 8)) == (pref >> (pos + 8)));
            if (act) atomicAdd(&hist[(unsigned)(key >> pos) & 255u], 1u);
        }
        __syncthreads();
        if (tid == 0) {
            int k = skrem;
            int v = 255;
            while (v > 0 && (int)hist[v] < k) { k -= (int)hist[v]; v--; }
            skrem = k;
            sprefix = pref | ((unsigned long long)(unsigned)v << pos);
        }
        __syncthreads();
    }
    unsigned long long kth = sprefix;
    for (int i = tid; i < NPTS; i += 256)
        fgmask[b * NPTS + i] = (makeKey(M[i], i) >= kth) ? 1 : 0;
}

// ---------------------------------------------------------------------------
// masked FPS (unchanged from round 3)
// ---------------------------------------------------------------------------
template<int J>
__device__ __forceinline__ void fps_body(
    const float2* __restrict__ xy, const float* __restrict__ zs,
    const int* __restrict__ pidbuf, const float* __restrict__ X,
    int outBase, int* __restrict__ idxInt, float* __restrict__ idxOutF,
    float* rv, int* ri, float* swin)
{
    int tid = threadIdx.x;
    int lane = tid & 31, wid = tid >> 5;

    float mind[J];
    int pid[J];
#pragma unroll
    for (int j = 0; j < J; j++) { mind[j] = 1e10f; pid[j] = pidbuf[j * 1024 + tid]; }

    float bv = 1e10f;
    int bi = pid[0];
#pragma unroll
    for (int j = 1; j < J; j++) bi = min(bi, pid[j]);

    for (int it = 0; it < FG_NS; it++) {
#pragma unroll
        for (int off = 16; off; off >>= 1) {
            float ov = __shfl_down_sync(0xFFFFFFFFu, bv, off);
            int   oi = __shfl_down_sync(0xFFFFFFFFu, bi, off);
            if (ov > bv || (ov == bv && oi < bi)) { bv = ov; bi = oi; }
        }
        if (lane == 0) { rv[wid] = bv; ri[wid] = bi; }
        __syncthreads();
        if (wid == 0) {
            bv = rv[lane]; bi = ri[lane];
#pragma unroll
            for (int off = 16; off; off >>= 1) {
                float ov = __shfl_down_sync(0xFFFFFFFFu, bv, off);
                int   oi = __shfl_down_sync(0xFFFFFFFFu, bi, off);
                if (ov > bv || (ov == bv && oi < bi)) { bv = ov; bi = oi; }
            }
            if (lane == 0) {
                idxInt[outBase + it] = bi;
                idxOutF[outBase + it] = (float)bi;
                swin[0] = X[bi * 3 + 0];
                swin[1] = X[bi * 3 + 1];
                swin[2] = X[bi * 3 + 2];
            }
        }
        __syncthreads();
        float sx = swin[0], sy = swin[1], sz = swin[2];
        bv = -4.f; bi = 0x7FFFFFFF;
#pragma unroll
        for (int j = 0; j < J; j++) {
            float2 p = xy[j * 1024 + tid];
            float pz = zs[j * 1024 + tid];
            float dx = __fsub_rn(p.x, sx);
            float dy = __fsub_rn(p.y, sy);
            float dz = __fsub_rn(pz, sz);
            float d = __fadd_rn(__fadd_rn(__fmul_rn(dx, dx), __fmul_rn(dy, dy)),
                                __fmul_rn(dz, dz));
            float m = fminf(mind[j], d);
            mind[j] = m;
            if (m > bv || (m == bv && pid[j] < bi)) { bv = m; bi = pid[j]; }
        }
    }
}

__global__ void __launch_bounds__(1024, 1) fps_kernel(
    const float* __restrict__ xyz, const int* __restrict__ fgmask,
    int* __restrict__ fpsPid, int* __restrict__ idxInt, float* __restrict__ idxOutF)
{
    extern __shared__ float sh[];
    float2* xy = (float2*)sh;
    float* zs = sh + 2 * 14336;
    __shared__ int scnt;
    __shared__ float rv[32];
    __shared__ int ri[32];
    __shared__ float swin[3];

    int blk = blockIdx.x;
    int b = blk >> 1;
    int isFg = !(blk & 1);
    const float* X = xyz + (size_t)b * NPTS * 3;
    const int* Mk = fgmask + b * NPTS;
    int* pidbuf = fpsPid + blk * 14336;
    int tid = threadIdx.x;

    if (tid == 0) scnt = 0;
    __syncthreads();
    for (int i = tid; i < NPTS; i += 1024) {
        int m = Mk[i];
        if (!isFg) m = !m;
        if (m) {
            int pos = atomicAdd(&scnt, 1);
            xy[pos] = make_float2(X[i * 3 + 0], X[i * 3 + 1]);
            zs[pos] = X[i * 3 + 2];
            pidbuf[pos] = i;
        }
    }
    __syncthreads();

    int outBase = b * NPOINT + (isFg ? 0 : FG_NS);
    if (isFg)
        fps_body<2>(xy, zs, pidbuf, X, outBase, idxInt, idxOutF, rv, ri, swin);
    else
        fps_body<14>(xy, zs, pidbuf, X, outBase, idxInt, idxOutF, rv, ri, swin);
}

// ---------------------------------------------------------------------------
// gather sampled centroids
// ---------------------------------------------------------------------------
__global__ void gathernew_kernel(const float* __restrict__ xyz, const int* __restrict__ idxInt,
                                 float* __restrict__ newxyz, float* __restrict__ outXyz)
{
    int t = blockIdx.x * blockDim.x + threadIdx.x;   // 12288
    int d = t % 3;
    int rest = t / 3;
    int b = rest >> 10, s = rest & 1023;
    int i = idxInt[b * NPOINT + s];
    float v = xyz[((size_t)b * NPTS + i) * 3 + d];
    newxyz[t] = v;
    outXyz[t] = v;
}

// ---------------------------------------------------------------------------
// ball query: one warp per query
// ---------------------------------------------------------------------------
__global__ void ballq_kernel(const float* __restrict__ xyz, const float* __restrict__ newxyz,
                             int* __restrict__ ballIdx)
{
    __shared__ int lists[8][32];
    int warp = threadIdx.x >> 5, lane = threadIdx.x & 31;
    int q = blockIdx.x * 8 + warp;
    int b = q >> 10;
    const float* X = xyz + (size_t)b * NPTS * 3;
    float qx = newxyz[q * 3], qy = newxyz[q * 3 + 1], qz = newxyz[q * 3 + 2];
    const float R2 = (float)(0.3 * 0.3);
    int cnt = 0;
    for (int chunk = 0; chunk < NPTS / 32; chunk++) {
        int p = chunk * 32 + lane;
        float dx = __fsub_rn(qx, X[p * 3 + 0]);
        float dy = __fsub_rn(qy, X[p * 3 + 1]);
        float dz = __fsub_rn(qz, X[p * 3 + 2]);
        float d2 = __fadd_rn(__fadd_rn(__fmul_rn(dx, dx), __fmul_rn(dy, dy)),
                             __fmul_rn(dz, dz));
        bool in = (d2 <= R2);
        unsigned m = __ballot_sync(0xFFFFFFFFu, in);
        if (m) {
            int pos = cnt + __popc(m & ((1u << lane) - 1u));
            if (in && pos < 32) lists[warp][pos] = p;
            cnt += __popc(m);
            if (cnt >= 32) break;
        }
    }
    __syncwarp();
    int c = cnt < 32 ? cnt : 32;
    int v = (lane < c) ? lists[warp][lane] : lists[warp][0];
    ballIdx[q * 32 + lane] = v;
}

// ---------------------------------------------------------------------------
// build transposed grouped input xbufT[131072][160]
// ---------------------------------------------------------------------------
__global__ void buildxT_kernel(const float* __restrict__ xyz, const float* __restrict__ features,
                               const float* __restrict__ newxyz, const int* __restrict__ ballIdx,
                               float* __restrict__ xbufT)
{
    int t = blockIdx.x * blockDim.x + threadIdx.x;  // 131072*160
    int c = t % KX1;
    int col = t / KX1;
    float v = 0.f;
    if (c < 131) {
        int b = col >> 15, s = (col >> 5) & 1023;
        int idx = ballIdx[col];
        if (c < 3)
            v = __fsub_rn(xyz[((size_t)b * NPTS + idx) * 3 + c],
                          newxyz[((b << 10) + s) * 3 + c]);
        else
            v = features[((size_t)b * CIN + (c - 3)) * NPTS + idx];
    }
    xbufT[t] = v;
}

// ---------------------------------------------------------------------------
// final maxpool: pick max (a>=0) or min (a<0) of raw y3, apply BN3 + relu
// ---------------------------------------------------------------------------
__global__ void maxpool_final(const float* __restrict__ pmax, const float* __restrict__ pmin,
                              float* __restrict__ outFeat)
{
    int t = blockIdx.x * blockDim.x + threadIdx.x;   // 1048576
    int m = t >> 12;
    int cent = t & 4095;
    float a = g_aff_a[3][m], c = g_aff_c[3][m];
    float y = (a >= 0.f) ? pmax[t] : pmin[t];
    float v = fmaxf(fmaf(a, y, c), 0.f);
    int b = cent >> 10, s = cent & 1023;
    outFeat[(((size_t)b * 256 + m) << 10) + s] = v;
}

// ---------------------------------------------------------------------------
// host launcher
// ---------------------------------------------------------------------------
extern "C" void kernel_launch(void* const* d_in, const int* in_sizes, int n_in,
                              void* d_out, int out_size)
{
    const float* xyz      = (const float*)d_in[0];
    const float* features = (const float*)d_in[1];
    const float* w1  = (const float*)d_in[2];
    const float* g1  = (const float*)d_in[3];
    const float* b1  = (const float*)d_in[4];
    const float* w2  = (const float*)d_in[5];
    const float* g2  = (const float*)d_in[6];
    const float* b2  = (const float*)d_in[7];
    const float* w3  = (const float*)d_in[8];
    const float* g3  = (const float*)d_in[9];
    const float* b3  = (const float*)d_in[10];
    const float* fw1 = (const float*)d_in[11];
    const float* fg1 = (const float*)d_in[12];
    const float* fb1 = (const float*)d_in[13];
    const float* fw2 = (const float*)d_in[14];
    const float* fbias2 = (const float*)d_in[15];

    float* out = (float*)d_out;
    float* outXyz    = out + OFS_XYZ;
    float* outFeat   = out + OFS_FEAT;
    float* outIdx    = out + OFS_IDX;
    float* outScores = out + OFS_SCORES;

    float* scr = nullptr;
    cudaGetSymbolAddress((void**)&scr, g_scratch);
    float* y1d    = scr + O_Y1D;
    float* xbufT  = scr + O_XT;
    float* y1T    = scr + O_Y1T;
    float* y2T    = scr + O_Y2T;
    float* p3max  = scr + O_P3MAX;
    float* p3min  = scr + O_P3MIN;
    float* margin = scr + O_MARGIN;
    float* newxyz = scr + O_NEWXYZ;
    float* wpad   = scr + O_WPAD;
    int* fgmask   = (int*)(scr + O_FGMASK);
    int* idxInt   = (int*)(scr + O_INDICES);
    int* ballIdx  = (int*)(scr + O_BALL);
    int* fpsPid   = (int*)(scr + O_FPSPID);

    zero_stats_kernel<<<1, 256>>>();
    padw_kernel<<<(128 * KX1) / 256, 256>>>(w1, wpad);

    // mask-head conv (fp32 exact, M=64, K=128); stats fused (layer 0)
    gemm_fused<4><<<dim3(NCOLS1D / 128, 1), 256>>>(
        fw1, features, y1d, 128, NCOLS1D, -1, 1, 0);
    finalize_kernel<<<1, 256>>>(64, fg1, fb1, 0, (double)NCOLS1D);

    maskhead_kernel<<<NCOLS1D / 256, 256>>>(y1d, fw2, fbias2, outScores, margin);
    select_kernel<<<4, 256>>>(margin, fgmask);

    cudaFuncSetAttribute(fps_kernel, cudaFuncAttributeMaxDynamicSharedMemorySize, 14336 * 3 * 4);
    fps_kernel<<<8, 1024, 14336 * 3 * 4>>>(xyz, fgmask, fpsPid, idxInt, outIdx);

    gathernew_kernel<<<12288 / 256, 256>>>(xyz, idxInt, newxyz, outXyz);
    ballq_kernel<<<NPOINT * BATCH / 8, 256>>>(xyz, newxyz, ballIdx);
    buildxT_kernel<<<(NCOLS2D * KX1) / 256, 256>>>(xyz, features, newxyz, ballIdx, xbufT);

    // conv1: tf32 mma.sync, K=160(padded); stats layer 1
    {
        auto k = conv_mma<KX1, -1, 1, 0>;
        size_t sm = (size_t)2 * 128 * (KX1 + 4) * 4;
        cudaFuncSetAttribute(k, cudaFuncAttributeMaxDynamicSharedMemorySize, (int)sm);
        k<<<dim3(NCOLS2D / 128, 1), 256, sm>>>(wpad, xbufT, y1T, nullptr, nullptr);
    }
    finalize_kernel<<<1, 256>>>(128, g1, b1, 1, (double)NCOLS2D);

    // conv2: BN1+relu on B-load; stats layer 2
    {
        auto k = conv_mma<128, 1, 2, 0>;
        size_t sm = (size_t)2 * 128 * 132 * 4;
        cudaFuncSetAttribute(k, cudaFuncAttributeMaxDynamicSharedMemorySize, (int)sm);
        k<<<dim3(NCOLS2D / 128, 1), 256, sm>>>(w2, y1T, y2T, nullptr, nullptr);
    }
    finalize_kernel<<<1, 256>>>(128, g2, b2, 2, (double)NCOLS2D);

    // conv3: M=256 via grid.y=2, BN2+relu on B-load; stats layer 3 + pool
    {
        auto k = conv_mma<128, 2, 3, 1>;
        size_t sm = (size_t)2 * 128 * 132 * 4;
        cudaFuncSetAttribute(k, cudaFuncAttributeMaxDynamicSharedMemorySize, (int)sm);
        k<<<dim3(NCOLS2D / 128, 2), 256, sm>>>(w3, y2T, nullptr, p3max, p3min);
    }
    finalize_kernel<<<1, 256>>>(256, g3, b3, 3, (double)NCOLS2D);

    maxpool_final<<<(256 * 4096) / 256, 256>>>(p3max, p3min, outFeat);
}

// round 7
// speedup vs baseline: 2.4240x; 1.4673x over previous
#include <cuda_runtime.h>
#include <cuda_bf16.h>
#include <cstdint>

#define BATCH   4
#define NPTS    16384
#define CIN     128
#define NPOINT  1024
#define FG_NS   512
#define TOPK_K  2048
#define NCOLS2D 131072
#define NCOLS1D 65536
#define KX1     160

#define OFS_XYZ    0
#define OFS_FEAT   12288
#define OFS_IDX    (12288 + 1048576)
#define OFS_SCORES (12288 + 1048576 + 4096)

#define O_Y1D     0ull
#define O_XT      4194304ull
#define O_Y1T     25165824ull
#define O_Y2T     41943040ull
#define O_P3MAX   58720256ull
#define O_P3MIN   59768832ull
#define O_MARGIN  60817408ull
#define O_NEWXYZ  60882944ull
#define O_FGMASK  60895232ull
#define O_INDICES 60960768ull
#define O_BALL    60964864ull
#define O_WPAD    61095936ull
#define O_FEATT   61116416ull
#define SCRATCH_FLOATS 69505024ull

__device__ float g_scratch[SCRATCH_FLOATS];
__device__ double g_sum[4][256];
__device__ double g_sumsq[4][256];

// ---------------------------------------------------------------------------
__device__ __forceinline__ float tf32r(float x) {
    uint32_t u;
    asm("cvt.rna.tf32.f32 %0, %1;" : "=r"(u) : "f"(x));
    return __uint_as_float(u);
}
__device__ __forceinline__ void mma_tf32(float* c, uint32_t a0, uint32_t a1,
                                         uint32_t a2, uint32_t a3,
                                         uint32_t b0, uint32_t b1) {
    asm("mma.sync.aligned.m16n8k8.row.col.f32.tf32.tf32.f32 "
        "{%0,%1,%2,%3},{%4,%5,%6,%7},{%8,%9},{%0,%1,%2,%3};"
        : "+f"(c[0]), "+f"(c[1]), "+f"(c[2]), "+f"(c[3])
        : "r"(a0), "r"(a1), "r"(a2), "r"(a3), "r"(b0), "r"(b1));
}
__device__ __forceinline__ void bn_affine(int layer, int m, double cnt,
                                          const float* g, const float* beta,
                                          float& a, float& c) {
    double mu = g_sum[layer][m] / cnt;
    double var = g_sumsq[layer][m] / cnt - mu * mu;
    a = g[m] * rsqrtf((float)var + 1e-5f);
    c = beta[m] - (float)mu * a;
}

// ---------------------------------------------------------------------------
__global__ void prep_kernel(const float* __restrict__ w1, float* __restrict__ wpad) {
    int t = blockIdx.x * blockDim.x + threadIdx.x;   // 80*256 = 20480 = 128*160
    if (blockIdx.x == 0) {
        double* s  = &g_sum[0][0];
        double* s2 = &g_sumsq[0][0];
        for (int i = threadIdx.x; i < 4 * 256; i += 256) { s[i] = 0.0; s2[i] = 0.0; }
    }
    int o = t / KX1, c = t % KX1;
    wpad[t] = (c < 131) ? w1[o * 131 + c] : 0.f;
}

__global__ void transpose_kernel(const float* __restrict__ features,
                                 float* __restrict__ featT)
{
    __shared__ float tile[32][33];
    int b = blockIdx.z;
    int n0 = blockIdx.x * 32, c0 = blockIdx.y * 32;
    int x = threadIdx.x, y = threadIdx.y;          // block 32x8
#pragma unroll
    for (int k = 0; k < 32; k += 8)
        tile[y + k][x] = features[((size_t)b * CIN + c0 + y + k) * NPTS + n0 + x];
    __syncthreads();
#pragma unroll
    for (int k = 0; k < 32; k += 8)
        featT[((size_t)b * NPTS + n0 + y + k) * CIN + c0 + x] = tile[x][y + k];
}

// ---------------------------------------------------------------------------
// tf32 mma.sync conv GEMM (BN-finalize preamble fused)
// ---------------------------------------------------------------------------
template<int KE, int AFF, int STATS, int POOL>
__global__ void __launch_bounds__(256, 1) conv_mma(
    const float* __restrict__ W, const float* __restrict__ Xin,
    float* __restrict__ Yout, float* __restrict__ poolMax, float* __restrict__ poolMin,
    const float* __restrict__ gPrev, const float* __restrict__ bPrev)
{
    constexpr int LDK = KE + 4;
    extern __shared__ float sm[];
    float* As = sm;
    float* Bs = sm + 128 * LDK;
    __shared__ __align__(16) float affA[128];
    __shared__ __align__(16) float affC[128];
    const int tid = threadIdx.x;
    const int wid = tid >> 5, lane = tid & 31;
    const int g = lane >> 2, t = lane & 3;
    const int wm = wid >> 2, wn = wid & 3;
    const int rowBase = blockIdx.y * 128;
    const int colBase = blockIdx.x * 128;

    if (AFF >= 0) {
        if (tid < 128)
            bn_affine(AFF, tid, (double)NCOLS2D, gPrev, bPrev, affA[tid], affC[tid]);
        __syncthreads();
    }
    for (int i = tid; i < 128 * (KE / 4); i += 256) {
        int r = i / (KE / 4), k = (i % (KE / 4)) * 4;
        float4 v = *(const float4*)(W + (size_t)(rowBase + r) * KE + k);
        As[r * LDK + k + 0] = tf32r(v.x);
        As[r * LDK + k + 1] = tf32r(v.y);
        As[r * LDK + k + 2] = tf32r(v.z);
        As[r * LDK + k + 3] = tf32r(v.w);
    }
    for (int i = tid; i < 128 * (KE / 4); i += 256) {
        int r = i / (KE / 4), k = (i % (KE / 4)) * 4;
        float4 v = *(const float4*)(Xin + (size_t)(colBase + r) * KE + k);
        if (AFF >= 0) {
            float4 av = *(const float4*)&affA[k];
            float4 cv = *(const float4*)&affC[k];
            v.x = fmaxf(fmaf(av.x, v.x, cv.x), 0.f);
            v.y = fmaxf(fmaf(av.y, v.y, cv.y), 0.f);
            v.z = fmaxf(fmaf(av.z, v.z, cv.z), 0.f);
            v.w = fmaxf(fmaf(av.w, v.w, cv.w), 0.f);
        }
        Bs[r * LDK + k + 0] = tf32r(v.x);
        Bs[r * LDK + k + 1] = tf32r(v.y);
        Bs[r * LDK + k + 2] = tf32r(v.z);
        Bs[r * LDK + k + 3] = tf32r(v.w);
    }
    __syncthreads();

    float acc[4][4][4];
#pragma unroll
    for (int i = 0; i < 4; i++)
#pragma unroll
        for (int j = 0; j < 4; j++)
#pragma unroll
            for (int c = 0; c < 4; c++) acc[i][j][c] = 0.f;

    const float* Arow0 = As + (size_t)(wm * 64 + g) * LDK + t;
    const float* Arow8 = Arow0 + 8 * LDK;
    const float* Bcol0 = Bs + (size_t)(wn * 32 + g) * LDK + t;

#pragma unroll 4
    for (int ks = 0; ks < KE / 8; ks++) {
        const int k0 = ks * 8;
        uint32_t a[4][4], b[4][2];
#pragma unroll
        for (int ma = 0; ma < 4; ma++) {
            const float* p0 = Arow0 + ma * 16 * LDK + k0;
            const float* p8 = Arow8 + ma * 16 * LDK + k0;
            a[ma][0] = __float_as_uint(p0[0]);
            a[ma][1] = __float_as_uint(p8[0]);
            a[ma][2] = __float_as_uint(p0[4]);
            a[ma][3] = __float_as_uint(p8[4]);
        }
#pragma unroll
        for (int nb = 0; nb < 4; nb++) {
            const float* pb = Bcol0 + nb * 8 * LDK + k0;
            b[nb][0] = __float_as_uint(pb[0]);
            b[nb][1] = __float_as_uint(pb[4]);
        }
#pragma unroll
        for (int ma = 0; ma < 4; ma++)
#pragma unroll
            for (int nb = 0; nb < 4; nb++)
                mma_tf32(acc[ma][nb], a[ma][0], a[ma][1], a[ma][2], a[ma][3],
                         b[nb][0], b[nb][1]);
    }

#pragma unroll
    for (int ma = 0; ma < 4; ma++) {
        int r0 = wm * 64 + ma * 16 + g;
        float s0 = 0.f, q0 = 0.f, s1 = 0.f, q1 = 0.f;
        float mx0 = -1e30f, mn0 = 1e30f, mx1 = -1e30f, mn1 = 1e30f;
#pragma unroll
        for (int nb = 0; nb < 4; nb++) {
            float c0 = acc[ma][nb][0], c1 = acc[ma][nb][1];
            float c2 = acc[ma][nb][2], c3 = acc[ma][nb][3];
            s0 += c0 + c1; q0 = fmaf(c0, c0, fmaf(c1, c1, q0));
            s1 += c2 + c3; q1 = fmaf(c2, c2, fmaf(c3, c3, q1));
            if (POOL) {
                mx0 = fmaxf(mx0, fmaxf(c0, c1)); mn0 = fminf(mn0, fminf(c0, c1));
                mx1 = fmaxf(mx1, fmaxf(c2, c3)); mn1 = fminf(mn1, fminf(c2, c3));
            }
        }
#pragma unroll
        for (int off = 1; off < 4; off <<= 1) {
            s0 += __shfl_xor_sync(0xFFFFFFFFu, s0, off);
            q0 += __shfl_xor_sync(0xFFFFFFFFu, q0, off);
            s1 += __shfl_xor_sync(0xFFFFFFFFu, s1, off);
            q1 += __shfl_xor_sync(0xFFFFFFFFu, q1, off);
            if (POOL) {
                mx0 = fmaxf(mx0, __shfl_xor_sync(0xFFFFFFFFu, mx0, off));
                mn0 = fminf(mn0, __shfl_xor_sync(0xFFFFFFFFu, mn0, off));
                mx1 = fmaxf(mx1, __shfl_xor_sync(0xFFFFFFFFu, mx1, off));
                mn1 = fminf(mn1, __shfl_xor_sync(0xFFFFFFFFu, mn1, off));
            }
        }
        if (t == 0) {
            atomicAdd(&g_sum[STATS][rowBase + r0], (double)s0);
            atomicAdd(&g_sumsq[STATS][rowBase + r0], (double)q0);
            atomicAdd(&g_sum[STATS][rowBase + r0 + 8], (double)s1);
            atomicAdd(&g_sumsq[STATS][rowBase + r0 + 8], (double)q1);
            if (POOL) {
                int cent = (colBase >> 5) + wn;
                poolMax[(size_t)(rowBase + r0) * 4096 + cent] = mx0;
                poolMin[(size_t)(rowBase + r0) * 4096 + cent] = mn0;
                poolMax[(size_t)(rowBase + r0 + 8) * 4096 + cent] = mx1;
                poolMin[(size_t)(rowBase + r0 + 8) * 4096 + cent] = mn1;
            }
        }
    }

    if (!POOL) {
        __syncthreads();
        float* Ct = As;   // [128 cols][132]
#pragma unroll
        for (int ma = 0; ma < 4; ma++) {
            int r0 = wm * 64 + ma * 16 + g;
#pragma unroll
            for (int nb = 0; nb < 4; nb++) {
                int col0 = wn * 32 + nb * 8 + 2 * t;
                Ct[col0 * 132 + r0]           = acc[ma][nb][0];
                Ct[(col0 + 1) * 132 + r0]     = acc[ma][nb][1];
                Ct[col0 * 132 + r0 + 8]       = acc[ma][nb][2];
                Ct[(col0 + 1) * 132 + r0 + 8] = acc[ma][nb][3];
            }
        }
        __syncthreads();
        for (int i = tid; i < 128 * 32; i += 256) {
            int col = i >> 5;
            int r4 = (i & 31) * 4;
            float4 v = *(float4*)&Ct[col * 132 + r4];
            *(float4*)(Yout + (size_t)(colBase + col) * 128 + r4) = v;
        }
    }
}

// ---------------------------------------------------------------------------
// SIMT SGEMM for mask-head conv (fp32 exact, B = features layout), stats fused
// ---------------------------------------------------------------------------
template<int RT>
__global__ void __launch_bounds__(256, 2) gemm_fused(
    const float* __restrict__ A, const float* __restrict__ B, float* __restrict__ C,
    int K, int Ncols, int statsLayer)
{
    constexpr int TM = RT * 16;
    __shared__ float As[2][16][TM + 4];
    __shared__ float Bs[2][16][128];
    const int tid = threadIdx.x;
    const int tx = tid & 15, ty = tid >> 4;
    const int rowBase = blockIdx.y * TM;
    const int colBase = blockIdx.x * 128;

    float acc[RT][8];
#pragma unroll
    for (int i = 0; i < RT; i++)
#pragma unroll
        for (int j = 0; j < 8; j++) acc[i][j] = 0.f;

    const int ktiles = K >> 4;
    {
#pragma unroll
        for (int l = 0; l < RT; l++) {
            int i = l * 256 + tid;
            int r = i >> 4, kk = i & 15;
            As[0][kk][r] = A[(rowBase + r) * K + kk];
        }
#pragma unroll
        for (int l = 0; l < 2; l++) {
            int i = l * 256 + tid;
            int kk = i >> 5, c4 = i & 31;
            int gc = colBase + c4 * 4;
            const float* src = B + (((size_t)(gc >> 14) * 128 + kk) << 14) + (gc & 16383);
            *(float4*)&Bs[0][kk][c4 * 4] = *(const float4*)src;
        }
    }
    __syncthreads();

    float pa[RT];
    float4 pb0, pb1;
    for (int kt = 0; kt < ktiles; kt++) {
        const int cur = kt & 1, nxt = cur ^ 1;
        const bool more = (kt + 1 < ktiles);
        if (more) {
            const int k0 = (kt + 1) << 4;
#pragma unroll
            for (int l = 0; l < RT; l++) {
                int i = l * 256 + tid;
                int r = i >> 4, kk = i & 15;
                pa[l] = A[(rowBase + r) * K + k0 + kk];
            }
#pragma unroll
            for (int l = 0; l < 2; l++) {
                int i = l * 256 + tid;
                int kk = i >> 5, c4 = i & 31;
                int gk = k0 + kk, gc = colBase + c4 * 4;
                const float* src = B + (((size_t)(gc >> 14) * 128 + gk) << 14) + (gc & 16383);
                float4 v = *(const float4*)src;
                if (l == 0) pb0 = v; else pb1 = v;
            }
        }
#pragma unroll
        for (int kk = 0; kk < 16; kk++) {
            float ra[RT], rb[8];
#pragma unroll
            for (int i = 0; i < RT; i++) ra[i] = As[cur][kk][ty * RT + i];
#pragma unroll
            for (int j = 0; j < 8; j++) rb[j] = Bs[cur][kk][tx * 8 + j];
#pragma unroll
            for (int i = 0; i < RT; i++)
#pragma unroll
                for (int j = 0; j < 8; j++)
                    acc[i][j] = fmaf(ra[i], rb[j], acc[i][j]);
        }
        if (more) {
#pragma unroll
            for (int l = 0; l < RT; l++) {
                int i = l * 256 + tid;
                int r = i >> 4, kk = i & 15;
                As[nxt][kk][r] = pa[l];
            }
            { int kk = tid >> 5, c4 = tid & 31; *(float4*)&Bs[nxt][kk][c4 * 4] = pb0; }
            { int i = 256 + tid; int kk = i >> 5, c4 = i & 31; *(float4*)&Bs[nxt][kk][c4 * 4] = pb1; }
        }
        __syncthreads();
    }
#pragma unroll
    for (int i = 0; i < RT; i++) {
        float* dst = C + (size_t)(rowBase + ty * RT + i) * Ncols + colBase + tx * 8;
        *(float4*)dst       = make_float4(acc[i][0], acc[i][1], acc[i][2], acc[i][3]);
        *(float4*)(dst + 4) = make_float4(acc[i][4], acc[i][5], acc[i][6], acc[i][7]);
    }
#pragma unroll
    for (int i = 0; i < RT; i++) {
        float s = 0.f, s2 = 0.f;
#pragma unroll
        for (int j = 0; j < 8; j++) { float v = acc[i][j]; s += v; s2 = fmaf(v, v, s2); }
#pragma unroll
        for (int off = 1; off < 16; off <<= 1) {
            s  += __shfl_xor_sync(0xFFFFFFFFu, s, off);
            s2 += __shfl_xor_sync(0xFFFFFFFFu, s2, off);
        }
        if (tx == 0) {
            int gr = rowBase + ty * RT + i;
            atomicAdd(&g_sum[statsLayer][gr], (double)s);
            atomicAdd(&g_sumsq[statsLayer][gr], (double)s2);
        }
    }
}

// ---------------------------------------------------------------------------
// mask head (BN0 finalize fused): scores + softmax margin
// ---------------------------------------------------------------------------
__global__ void maskhead_kernel(const float* __restrict__ y1d,
                                const float* __restrict__ fg1,
                                const float* __restrict__ fb1,
                                const float* __restrict__ fw2,
                                const float* __restrict__ fbias2,
                                float* __restrict__ outScores,
                                float* __restrict__ margin)
{
    __shared__ float affA[64], affC[64];
    if (threadIdx.x < 64)
        bn_affine(0, threadIdx.x, (double)NCOLS1D, fg1, fb1,
                  affA[threadIdx.x], affC[threadIdx.x]);
    __syncthreads();
    int col = blockIdx.x * blockDim.x + threadIdx.x;
    int b = col >> 14, n = col & 16383;
    float s0 = fbias2[0], s1 = fbias2[1];
#pragma unroll 4
    for (int c = 0; c < 64; c++) {
        float v = fmaxf(fmaf(affA[c], y1d[(size_t)c * NCOLS1D + col], affC[c]), 0.f);
        s0 = fmaf(fw2[c], v, s0);
        s1 = fmaf(fw2[64 + c], v, s1);
    }
    outScores[b * 32768 + n]         = s0;
    outScores[b * 32768 + 16384 + n] = s1;
    float mx = fmaxf(s0, s1);
    float e0 = expf(s0 - mx), e1 = expf(s1 - mx);
    margin[col] = (e1 - e0) / (e0 + e1);
}

// ---------------------------------------------------------------------------
// exact top-2048 per batch (radix select on 64-bit key)
// ---------------------------------------------------------------------------
__device__ __forceinline__ unsigned long long makeKey(float f, int i)
{
    unsigned u = __float_as_uint(f);
    u = (u & 0x80000000u) ? ~u : (u | 0x80000000u);
    return ((unsigned long long)u << 32) | (unsigned)(0xFFFFFFFFu - (unsigned)i);
}

__global__ void select_kernel(const float* __restrict__ margin, int* __restrict__ fgmask)
{
    __shared__ unsigned hist[256];
    __shared__ unsigned long long sprefix;
    __shared__ int skrem;
    int b = blockIdx.x, tid = threadIdx.x;
    const float* M = margin + b * NPTS;
    if (tid == 0) { sprefix = 0ull; skrem = TOPK_K; }
    __syncthreads();
    for (int pos = 56; pos >= 0; pos -= 8) {
        hist[tid] = 0;
        __syncthreads();
        unsigned long long pref = sprefix;
        for (int i = tid; i < NPTS; i += 256) {
            unsigned long long key = makeKey(M[i], i);
            bool act = (pos == 56) || ((key >> (pos + 8)) == (pref >> (pos + 8)));
            if (act) atomicAdd(&hist[(unsigned)(key >> pos) & 255u], 1u);
        }
        __syncthreads();
        if (tid == 0) {
            int k = skrem;
            int v = 255;
            while (v > 0 && (int)hist[v] < k) { k -= (int)hist[v]; v--; }
            skrem = k;
            sprefix = pref | ((unsigned long long)(unsigned)v << pos);
        }
        __syncthreads();
    }
    unsigned long long kth = sprefix;
    for (int i = tid; i < NPTS; i += 256)
        fgmask[b * NPTS + i] = (makeKey(M[i], i) >= kth) ? 1 : 0;
}

// ---------------------------------------------------------------------------
// masked FPS: Morton sort + warp-box pruning + redux reductions. Exact.
// ---------------------------------------------------------------------------
#define WSLOT 896
#define JFPS  28

__device__ __forceinline__ int spread3(int v) {
    return (v & 1) | ((v & 2) << 2) | ((v & 4) << 4);
}
__device__ __forceinline__ int cellOf(float x, float y, float z) {
    int cx = min(7, max(0, (int)(x * 8.f)));
    int cy = min(7, max(0, (int)(y * 8.f)));
    int cz = min(7, max(0, (int)(z * 8.f)));
    return spread3(cx) | (spread3(cy) << 1) | (spread3(cz) << 2);
}

__global__ void __launch_bounds__(512, 1) fps_kernel(
    const float* __restrict__ xyz, const int* __restrict__ fgmask,
    int* __restrict__ idxInt, float* __restrict__ idxOutF)
{
    extern __shared__ float4 pts[];            // 14336 float4
    __shared__ int hist[512];
    __shared__ uint2 warpRes[16];
    __shared__ float4 swin;

    const int blk = blockIdx.x, b = blk >> 1, isFg = !(blk & 1);
    const float* X = xyz + (size_t)b * NPTS * 3;
    const int* Mk = fgmask + b * NPTS;
    const int tid = threadIdx.x, lane = tid & 31, wid = tid >> 5;
    const int cnt = isFg ? TOPK_K : (NPTS - TOPK_K);      // 2048 / 14336
    const int padded = isFg ? 3 * WSLOT : 14336;          // 2688 / 14336
    const int nwActive = padded / WSLOT;                  // 3 / 16

    // histogram over 512 Morton cells
    hist[tid] = 0;
    __syncthreads();
    for (int i = tid; i < NPTS; i += 512) {
        int m = Mk[i]; if (!isFg) m = !m;
        if (m) atomicAdd(&hist[cellOf(X[i*3], X[i*3+1], X[i*3+2])], 1);
    }
    __syncthreads();
    // exclusive scan (scratch in pts area, pre-scatter)
    {
        int* sa = (int*)pts;
        int* sb = sa + 512;
        sa[tid] = hist[tid];
        __syncthreads();
        for (int off = 1; off < 512; off <<= 1) {
            int v = sa[tid] + (tid >= off ? sa[tid - off] : 0);
            __syncthreads();
            sb[tid] = v;
            int* tp = sa; sa = sb; sb = tp;
            __syncthreads();
        }
        int excl = sa[tid] - hist[tid];
        __syncthreads();
        hist[tid] = excl;
    }
    __syncthreads();
    // scatter (cell-sorted)
    for (int i = tid; i < NPTS; i += 512) {
        int m = Mk[i]; if (!isFg) m = !m;
        if (m) {
            float x = X[i*3], y = X[i*3+1], z = X[i*3+2];
            int pos = atomicAdd(&hist[cellOf(x, y, z)], 1);
            pts[pos] = make_float4(x, y, z, __int_as_float(i));
        }
    }
    __syncthreads();
    // pads (fg only): duplicate last real point; pid large -> loses ties
    for (int i = cnt + tid; i < padded; i += 512) {
        float4 p = pts[cnt - 1];
        pts[i] = p;               // same pid as last point: same selection result
    }
    __syncthreads();

    const bool act = wid < nwActive;
    const int wbase = wid * WSLOT;
    float mind[JFPS];
    uint32_t ppack[JFPS];
    float bxl = 1e9f, bxh = -1e9f, byl = 1e9f, byh = -1e9f, bzl = 1e9f, bzh = -1e9f;
    float bv;
    uint32_t bi;
    if (act) {
#pragma unroll
        for (int j = 0; j < JFPS; j++) {
            int slot = wbase + j * 32 + lane;
            float4 p = pts[slot];
            ppack[j] = ((uint32_t)__float_as_int(p.w) << 14) | (uint32_t)slot;
            mind[j] = 1e10f;
            bxl = fminf(bxl, p.x); bxh = fmaxf(bxh, p.x);
            byl = fminf(byl, p.y); byh = fmaxf(byh, p.y);
            bzl = fminf(bzl, p.z); bzh = fmaxf(bzh, p.z);
        }
#pragma unroll
        for (int off = 16; off; off >>= 1) {
            bxl = fminf(bxl, __shfl_xor_sync(0xFFFFFFFFu, bxl, off));
            bxh = fmaxf(bxh, __shfl_xor_sync(0xFFFFFFFFu, bxh, off));
            byl = fminf(byl, __shfl_xor_sync(0xFFFFFFFFu, byl, off));
            byh = fmaxf(byh, __shfl_xor_sync(0xFFFFFFFFu, byh, off));
            bzl = fminf(bzl, __shfl_xor_sync(0xFFFFFFFFu, bzl, off));
            bzh = fmaxf(bzh, __shfl_xor_sync(0xFFFFFFFFu, bzh, off));
        }
        bv = 1e10f;
        bi = 0xFFFFFFFFu;
#pragma unroll
        for (int j = 0; j < JFPS; j++) bi = min(bi, ppack[j]);
    } else {
        bv = 0.f; bi = 0xFFFFFFFFu;
    }

    const int outBase = b * NPOINT + (isFg ? 0 : FG_NS);
    for (int it = 0; it < FG_NS; it++) {
        uint32_t key = __float_as_uint(bv);
        uint32_t kmax = __reduce_max_sync(0xFFFFFFFFu, key);
        uint32_t cand = (key == kmax) ? bi : 0xFFFFFFFFu;
        uint32_t cmin = __reduce_min_sync(0xFFFFFFFFu, cand);
        if (lane == 0) warpRes[wid] = make_uint2(kmax, cmin);
        __syncthreads();
        if (wid == 0) {
            uint2 e = (lane < 16) ? warpRes[lane] : make_uint2(0u, 0xFFFFFFFFu);
            uint32_t k2 = __reduce_max_sync(0xFFFFFFFFu, e.x);
            uint32_t c2 = __reduce_min_sync(0xFFFFFFFFu,
                                            (e.x == k2) ? e.y : 0xFFFFFFFFu);
            if (lane == 0) {
                int pid = (int)(c2 >> 14);
                int slot = (int)(c2 & 0x3FFFu);
                idxInt[outBase + it] = pid;
                idxOutF[outBase + it] = (float)pid;
                swin = pts[slot];
            }
        }
        __syncthreads();
        float sx = swin.x, sy = swin.y, sz = swin.z;
        float dxc = fmaxf(fmaxf(__fsub_rn(bxl, sx), __fsub_rn(sx, bxh)), 0.f);
        float dyc = fmaxf(fmaxf(__fsub_rn(byl, sy), __fsub_rn(sy, byh)), 0.f);
        float dzc = fmaxf(fmaxf(__fsub_rn(bzl, sz), __fsub_rn(sz, bzh)), 0.f);
        float LB = dxc * dxc + dyc * dyc + dzc * dzc;
        float LBm = LB * 0.999f - 1e-6f;    // down-biased: skip is provably exact
        bool skip = !act || __all_sync(0xFFFFFFFFu, LBm >= bv);
        if (!skip) {
            float nbv = 0.f;
#pragma unroll
            for (int j = 0; j < JFPS; j++) {
                float4 p = pts[wbase + j * 32 + lane];
                float dx = __fsub_rn(p.x, sx);
                float dy = __fsub_rn(p.y, sy);
                float dz = __fsub_rn(p.z, sz);
                float d = __fadd_rn(__fadd_rn(__fmul_rn(dx, dx), __fmul_rn(dy, dy)),
                                    __fmul_rn(dz, dz));
                float m = fminf(mind[j], d);
                mind[j] = m;
                nbv = fmaxf(nbv, m);
            }
            uint32_t nbi = 0xFFFFFFFFu;
#pragma unroll
            for (int j = 0; j < JFPS; j++)
                nbi = (mind[j] == nbv) ? min(nbi, ppack[j]) : nbi;
            bv = nbv;
            bi = nbi;
        }
    }
}

// ---------------------------------------------------------------------------
// ball query + fused centroid gather: one warp per query
// ---------------------------------------------------------------------------
__global__ void ballq_kernel(const float* __restrict__ xyz, const int* __restrict__ idxInt,
                             float* __restrict__ newxyz, float* __restrict__ outXyz,
                             int* __restrict__ ballIdx)
{
    __shared__ int lists[8][32];
    int warp = threadIdx.x >> 5, lane = threadIdx.x & 31;
    int q = blockIdx.x * 8 + warp;
    int b = q >> 10;
    const float* X = xyz + (size_t)b * NPTS * 3;
    int sel = idxInt[q];
    float qx = X[sel * 3], qy = X[sel * 3 + 1], qz = X[sel * 3 + 2];
    if (lane < 3) {
        float v = X[sel * 3 + lane];
        newxyz[q * 3 + lane] = v;
        outXyz[q * 3 + lane] = v;
    }
    const float R2 = (float)(0.3 * 0.3);
    int cnt = 0;
    for (int chunk = 0; chunk < NPTS / 32; chunk++) {
        int p = chunk * 32 + lane;
        float dx = __fsub_rn(qx, X[p * 3 + 0]);
        float dy = __fsub_rn(qy, X[p * 3 + 1]);
        float dz = __fsub_rn(qz, X[p * 3 + 2]);
        float d2 = __fadd_rn(__fadd_rn(__fmul_rn(dx, dx), __fmul_rn(dy, dy)),
                             __fmul_rn(dz, dz));
        bool in = (d2 <= R2);
        unsigned m = __ballot_sync(0xFFFFFFFFu, in);
        if (m) {
            int pos = cnt + __popc(m & ((1u << lane) - 1u));
            if (in && pos < 32) lists[warp][pos] = p;
            cnt += __popc(m);
            if (cnt >= 32) break;
        }
    }
    __syncwarp();
    int c = cnt < 32 ? cnt : 32;
    int v = (lane < c) ? lists[warp][lane] : lists[warp][0];
    ballIdx[q * 32 + lane] = v;
}

// ---------------------------------------------------------------------------
// build transposed grouped input xbufT[131072][160]; coalesced featT reads
// ---------------------------------------------------------------------------
__global__ void buildxT_kernel(const float* __restrict__ xyz, const float* __restrict__ featT,
                               const float* __restrict__ newxyz, const int* __restrict__ ballIdx,
                               float* __restrict__ xbufT)
{
    int warp = threadIdx.x >> 5, lane = threadIdx.x & 31;
    int col = blockIdx.x * 8 + warp;
    int b = col >> 15, s = (col >> 5) & 1023;
    int idx = ballIdx[col];
    const float* fr = featT + ((size_t)b * NPTS + idx) * CIN;
    float* dst = xbufT + (size_t)col * KX1;
#pragma unroll
    for (int it = 0; it < 5; it++) {
        int c = it * 32 + lane;
        float v = 0.f;
        if (c < 3)
            v = __fsub_rn(xyz[((size_t)b * NPTS + idx) * 3 + c],
                          newxyz[((b << 10) + s) * 3 + c]);
        else if (c < 131)
            v = fr[c - 3];
        dst[c] = v;
    }
}

// ---------------------------------------------------------------------------
// final maxpool (BN3 finalize fused): max if a>=0 else min, then BN + relu
// ---------------------------------------------------------------------------
__global__ void maxpool_final(const float* __restrict__ pmax, const float* __restrict__ pmin,
                              const float* __restrict__ g3, const float* __restrict__ b3,
                              float* __restrict__ outFeat)
{
    __shared__ float sa_, sc_;
    int t = blockIdx.x * blockDim.x + threadIdx.x;   // 1048576
    int m = t >> 12;                                  // constant per 256-block
    if (threadIdx.x == 0) bn_affine(3, m, (double)NCOLS2D, g3, b3, sa_, sc_);
    __syncthreads();
    float a = sa_, c = sc_;
    int cent = t & 4095;
    float y = (a >= 0.f) ? pmax[t] : pmin[t];
    float v = fmaxf(fmaf(a, y, c), 0.f);
    int b = cent >> 10, s = cent & 1023;
    outFeat[(((size_t)b * 256 + m) << 10) + s] = v;
}

// ---------------------------------------------------------------------------
extern "C" void kernel_launch(void* const* d_in, const int* in_sizes, int n_in,
                              void* d_out, int out_size)
{
    const float* xyz      = (const float*)d_in[0];
    const float* features = (const float*)d_in[1];
    const float* w1  = (const float*)d_in[2];
    const float* g1  = (const float*)d_in[3];
    const float* b1  = (const float*)d_in[4];
    const float* w2  = (const float*)d_in[5];
    const float* g2  = (const float*)d_in[6];
    const float* b2  = (const float*)d_in[7];
    const float* w3  = (const float*)d_in[8];
    const float* g3  = (const float*)d_in[9];
    const float* b3  = (const float*)d_in[10];
    const float* fw1 = (const float*)d_in[11];
    const float* fg1 = (const float*)d_in[12];
    const float* fb1 = (const float*)d_in[13];
    const float* fw2 = (const float*)d_in[14];
    const float* fbias2 = (const float*)d_in[15];

    float* out = (float*)d_out;
    float* outXyz    = out + OFS_XYZ;
    float* outFeat   = out + OFS_FEAT;
    float* outIdx    = out + OFS_IDX;
    float* outScores = out + OFS_SCORES;

    float* scr = nullptr;
    cudaGetSymbolAddress((void**)&scr, g_scratch);
    float* y1d    = scr + O_Y1D;
    float* xbufT  = scr + O_XT;
    float* y1T    = scr + O_Y1T;
    float* y2T    = scr + O_Y2T;
    float* p3max  = scr + O_P3MAX;
    float* p3min  = scr + O_P3MIN;
    float* margin = scr + O_MARGIN;
    float* newxyz = scr + O_NEWXYZ;
    float* wpad   = scr + O_WPAD;
    float* featT  = scr + O_FEATT;
    int* fgmask   = (int*)(scr + O_FGMASK);
    int* idxInt   = (int*)(scr + O_INDICES);
    int* ballIdx  = (int*)(scr + O_BALL);

    prep_kernel<<<80, 256>>>(w1, wpad);
    transpose_kernel<<<dim3(NPTS / 32, CIN / 32, BATCH), dim3(32, 8)>>>(features, featT);

    gemm_fused<4><<<dim3(NCOLS1D / 128, 1), 256>>>(fw1, features, y1d, 128, NCOLS1D, 0);
    maskhead_kernel<<<NCOLS1D / 256, 256>>>(y1d, fg1, fb1, fw2, fbias2, outScores, margin);
    select_kernel<<<4, 256>>>(margin, fgmask);

    cudaFuncSetAttribute(fps_kernel, cudaFuncAttributeMaxDynamicSharedMemorySize, 14336 * 16);
    fps_kernel<<<8, 512, 14336 * 16>>>(xyz, fgmask, idxInt, outIdx);

    ballq_kernel<<<NPOINT * BATCH / 8, 256>>>(xyz, idxInt, newxyz, outXyz, ballIdx);
    buildxT_kernel<<<NCOLS2D / 8, 256>>>(xyz, featT, newxyz, ballIdx, xbufT);

    {
        auto k = conv_mma<KX1, -1, 1, 0>;
        size_t sm = (size_t)2 * 128 * (KX1 + 4) * 4;
        cudaFuncSetAttribute(k, cudaFuncAttributeMaxDynamicSharedMemorySize, (int)sm);
        k<<<dim3(NCOLS2D / 128, 1), 256, sm>>>(wpad, xbufT, y1T, nullptr, nullptr,
                                               nullptr, nullptr);
    }
    {
        auto k = conv_mma<128, 1, 2, 0>;
        size_t sm = (size_t)2 * 128 * 132 * 4;
        cudaFuncSetAttribute(k, cudaFuncAttributeMaxDynamicSharedMemorySize, (int)sm);
        k<<<dim3(NCOLS2D / 128, 1), 256, sm>>>(w2, y1T, y2T, nullptr, nullptr, g1, b1);
    }
    {
        auto k = conv_mma<128, 2, 3, 1>;
        size_t sm = (size_t)2 * 128 * 132 * 4;
        cudaFuncSetAttribute(k, cudaFuncAttributeMaxDynamicSharedMemorySize, (int)sm);
        k<<<dim3(NCOLS2D / 128, 2), 256, sm>>>(w3, y2T, nullptr, p3max, p3min, g2, b2);
    }
    maxpool_final<<<(256 * 4096) / 256, 256>>>(p3max, p3min, g3, b3, outFeat);
}

// round 8
// speedup vs baseline: 2.5301x; 1.0438x over previous
#include <cuda_runtime.h>
#include <cuda_bf16.h>
#include <cstdint>

#define BATCH   4
#define NPTS    16384
#define CIN     128
#define NPOINT  1024
#define FG_NS   512
#define TOPK_K  2048
#define NCOLS2D 131072
#define NCOLS1D 65536
#define KX1     160

#define OFS_XYZ    0
#define OFS_FEAT   12288
#define OFS_IDX    (12288 + 1048576)
#define OFS_SCORES (12288 + 1048576 + 4096)

#define O_Y1D     0ull
#define O_XT      4194304ull
#define O_Y1T     25165824ull
#define O_Y2T     41943040ull
#define O_P3MAX   58720256ull
#define O_P3MIN   59768832ull
#define O_MARGIN  60817408ull
#define O_NEWXYZ  60882944ull
#define O_FGMASK  60895232ull
#define O_INDICES 60960768ull
#define O_BALL    60964864ull
#define O_WPAD    61095936ull
#define O_FEATT   61116416ull
#define O_FPSPID  69505024ull
#define SCRATCH_FLOATS 69619712ull

__device__ float g_scratch[SCRATCH_FLOATS];
__device__ double g_sum[4][256];
__device__ double g_sumsq[4][256];

// ---------------------------------------------------------------------------
__device__ __forceinline__ float tf32r(float x) {
    uint32_t u;
    asm("cvt.rna.tf32.f32 %0, %1;" : "=r"(u) : "f"(x));
    return __uint_as_float(u);
}
__device__ __forceinline__ void mma_tf32(float* c, uint32_t a0, uint32_t a1,
                                         uint32_t a2, uint32_t a3,
                                         uint32_t b0, uint32_t b1) {
    asm("mma.sync.aligned.m16n8k8.row.col.f32.tf32.tf32.f32 "
        "{%0,%1,%2,%3},{%4,%5,%6,%7},{%8,%9},{%0,%1,%2,%3};"
        : "+f"(c[0]), "+f"(c[1]), "+f"(c[2]), "+f"(c[3])
        : "r"(a0), "r"(a1), "r"(a2), "r"(a3), "r"(b0), "r"(b1));
}
__device__ __forceinline__ void bn_affine(int layer, int m, double cnt,
                                          const float* g, const float* beta,
                                          float& a, float& c) {
    double mu = g_sum[layer][m] / cnt;
    double var = g_sumsq[layer][m] / cnt - mu * mu;
    a = g[m] * rsqrtf((float)var + 1e-5f);
    c = beta[m] - (float)mu * a;
}
// packed f32x2 helpers (per-element .rn semantics == scalar rn ops)
__device__ __forceinline__ unsigned long long pk2(float lo, float hi) {
    unsigned long long r;
    asm("mov.b64 %0, {%1, %2};" : "=l"(r) : "f"(lo), "f"(hi));
    return r;
}
__device__ __forceinline__ unsigned long long add2(unsigned long long a,
                                                   unsigned long long b) {
    unsigned long long d;
    asm("add.rn.f32x2 %0, %1, %2;" : "=l"(d) : "l"(a), "l"(b));
    return d;
}
__device__ __forceinline__ unsigned long long mul2(unsigned long long a,
                                                   unsigned long long b) {
    unsigned long long d;
    asm("mul.rn.f32x2 %0, %1, %2;" : "=l"(d) : "l"(a), "l"(b));
    return d;
}
__device__ __forceinline__ void upk2(unsigned long long v, float& lo, float& hi) {
    asm("mov.b64 {%0, %1}, %2;" : "=f"(lo), "=f"(hi) : "l"(v));
}

// ---------------------------------------------------------------------------
__global__ void prep_kernel(const float* __restrict__ w1, float* __restrict__ wpad) {
    int t = blockIdx.x * blockDim.x + threadIdx.x;   // 20480 = 128*160
    if (blockIdx.x == 0) {
        double* s  = &g_sum[0][0];
        double* s2 = &g_sumsq[0][0];
        for (int i = threadIdx.x; i < 4 * 256; i += 256) { s[i] = 0.0; s2[i] = 0.0; }
    }
    int o = t / KX1, c = t % KX1;
    wpad[t] = (c < 131) ? w1[o * 131 + c] : 0.f;
}

__global__ void transpose_kernel(const float* __restrict__ features,
                                 float* __restrict__ featT)
{
    __shared__ float tile[32][33];
    int b = blockIdx.z;
    int n0 = blockIdx.x * 32, c0 = blockIdx.y * 32;
    int x = threadIdx.x, y = threadIdx.y;
#pragma unroll
    for (int k = 0; k < 32; k += 8)
        tile[y + k][x] = features[((size_t)b * CIN + c0 + y + k) * NPTS + n0 + x];
    __syncthreads();
#pragma unroll
    for (int k = 0; k < 32; k += 8)
        featT[((size_t)b * NPTS + n0 + y + k) * CIN + c0 + x] = tile[x][y + k];
}

// ---------------------------------------------------------------------------
// tf32 mma.sync conv GEMM (BN-finalize preamble fused)
// ---------------------------------------------------------------------------
template<int KE, int AFF, int STATS, int POOL>
__global__ void __launch_bounds__(256, 1) conv_mma(
    const float* __restrict__ W, const float* __restrict__ Xin,
    float* __restrict__ Yout, float* __restrict__ poolMax, float* __restrict__ poolMin,
    const float* __restrict__ gPrev, const float* __restrict__ bPrev)
{
    constexpr int LDK = KE + 4;
    extern __shared__ float sm[];
    float* As = sm;
    float* Bs = sm + 128 * LDK;
    __shared__ __align__(16) float affA[128];
    __shared__ __align__(16) float affC[128];
    const int tid = threadIdx.x;
    const int wid = tid >> 5, lane = tid & 31;
    const int g = lane >> 2, t = lane & 3;
    const int wm = wid >> 2, wn = wid & 3;
    const int rowBase = blockIdx.y * 128;
    const int colBase = blockIdx.x * 128;

    if (AFF >= 0) {
        if (tid < 128)
            bn_affine(AFF, tid, (double)NCOLS2D, gPrev, bPrev, affA[tid], affC[tid]);
        __syncthreads();
    }
    for (int i = tid; i < 128 * (KE / 4); i += 256) {
        int r = i / (KE / 4), k = (i % (KE / 4)) * 4;
        float4 v = *(const float4*)(W + (size_t)(rowBase + r) * KE + k);
        As[r * LDK + k + 0] = tf32r(v.x);
        As[r * LDK + k + 1] = tf32r(v.y);
        As[r * LDK + k + 2] = tf32r(v.z);
        As[r * LDK + k + 3] = tf32r(v.w);
    }
    for (int i = tid; i < 128 * (KE / 4); i += 256) {
        int r = i / (KE / 4), k = (i % (KE / 4)) * 4;
        float4 v = *(const float4*)(Xin + (size_t)(colBase + r) * KE + k);
        if (AFF >= 0) {
            float4 av = *(const float4*)&affA[k];
            float4 cv = *(const float4*)&affC[k];
            v.x = fmaxf(fmaf(av.x, v.x, cv.x), 0.f);
            v.y = fmaxf(fmaf(av.y, v.y, cv.y), 0.f);
            v.z = fmaxf(fmaf(av.z, v.z, cv.z), 0.f);
            v.w = fmaxf(fmaf(av.w, v.w, cv.w), 0.f);
        }
        Bs[r * LDK + k + 0] = tf32r(v.x);
        Bs[r * LDK + k + 1] = tf32r(v.y);
        Bs[r * LDK + k + 2] = tf32r(v.z);
        Bs[r * LDK + k + 3] = tf32r(v.w);
    }
    __syncthreads();

    float acc[4][4][4];
#pragma unroll
    for (int i = 0; i < 4; i++)
#pragma unroll
        for (int j = 0; j < 4; j++)
#pragma unroll
            for (int c = 0; c < 4; c++) acc[i][j][c] = 0.f;

    const float* Arow0 = As + (size_t)(wm * 64 + g) * LDK + t;
    const float* Arow8 = Arow0 + 8 * LDK;
    const float* Bcol0 = Bs + (size_t)(wn * 32 + g) * LDK + t;

#pragma unroll 4
    for (int ks = 0; ks < KE / 8; ks++) {
        const int k0 = ks * 8;
        uint32_t a[4][4], b[4][2];
#pragma unroll
        for (int ma = 0; ma < 4; ma++) {
            const float* p0 = Arow0 + ma * 16 * LDK + k0;
            const float* p8 = Arow8 + ma * 16 * LDK + k0;
            a[ma][0] = __float_as_uint(p0[0]);
            a[ma][1] = __float_as_uint(p8[0]);
            a[ma][2] = __float_as_uint(p0[4]);
            a[ma][3] = __float_as_uint(p8[4]);
        }
#pragma unroll
        for (int nb = 0; nb < 4; nb++) {
            const float* pb = Bcol0 + nb * 8 * LDK + k0;
            b[nb][0] = __float_as_uint(pb[0]);
            b[nb][1] = __float_as_uint(pb[4]);
        }
#pragma unroll
        for (int ma = 0; ma < 4; ma++)
#pragma unroll
            for (int nb = 0; nb < 4; nb++)
                mma_tf32(acc[ma][nb], a[ma][0], a[ma][1], a[ma][2], a[ma][3],
                         b[nb][0], b[nb][1]);
    }

#pragma unroll
    for (int ma = 0; ma < 4; ma++) {
        int r0 = wm * 64 + ma * 16 + g;
        float s0 = 0.f, q0 = 0.f, s1 = 0.f, q1 = 0.f;
        float mx0 = -1e30f, mn0 = 1e30f, mx1 = -1e30f, mn1 = 1e30f;
#pragma unroll
        for (int nb = 0; nb < 4; nb++) {
            float c0 = acc[ma][nb][0], c1 = acc[ma][nb][1];
            float c2 = acc[ma][nb][2], c3 = acc[ma][nb][3];
            s0 += c0 + c1; q0 = fmaf(c0, c0, fmaf(c1, c1, q0));
            s1 += c2 + c3; q1 = fmaf(c2, c2, fmaf(c3, c3, q1));
            if (POOL) {
                mx0 = fmaxf(mx0, fmaxf(c0, c1)); mn0 = fminf(mn0, fminf(c0, c1));
                mx1 = fmaxf(mx1, fmaxf(c2, c3)); mn1 = fminf(mn1, fminf(c2, c3));
            }
        }
#pragma unroll
        for (int off = 1; off < 4; off <<= 1) {
            s0 += __shfl_xor_sync(0xFFFFFFFFu, s0, off);
            q0 += __shfl_xor_sync(0xFFFFFFFFu, q0, off);
            s1 += __shfl_xor_sync(0xFFFFFFFFu, s1, off);
            q1 += __shfl_xor_sync(0xFFFFFFFFu, q1, off);
            if (POOL) {
                mx0 = fmaxf(mx0, __shfl_xor_sync(0xFFFFFFFFu, mx0, off));
                mn0 = fminf(mn0, __shfl_xor_sync(0xFFFFFFFFu, mn0, off));
                mx1 = fmaxf(mx1, __shfl_xor_sync(0xFFFFFFFFu, mx1, off));
                mn1 = fminf(mn1, __shfl_xor_sync(0xFFFFFFFFu, mn1, off));
            }
        }
        if (t == 0) {
            atomicAdd(&g_sum[STATS][rowBase + r0], (double)s0);
            atomicAdd(&g_sumsq[STATS][rowBase + r0], (double)q0);
            atomicAdd(&g_sum[STATS][rowBase + r0 + 8], (double)s1);
            atomicAdd(&g_sumsq[STATS][rowBase + r0 + 8], (double)q1);
            if (POOL) {
                int cent = (colBase >> 5) + wn;
                poolMax[(size_t)(rowBase + r0) * 4096 + cent] = mx0;
                poolMin[(size_t)(rowBase + r0) * 4096 + cent] = mn0;
                poolMax[(size_t)(rowBase + r0 + 8) * 4096 + cent] = mx1;
                poolMin[(size_t)(rowBase + r0 + 8) * 4096 + cent] = mn1;
            }
        }
    }

    if (!POOL) {
        __syncthreads();
        float* Ct = As;   // [128 cols][132]
#pragma unroll
        for (int ma = 0; ma < 4; ma++) {
            int r0 = wm * 64 + ma * 16 + g;
#pragma unroll
            for (int nb = 0; nb < 4; nb++) {
                int col0 = wn * 32 + nb * 8 + 2 * t;
                Ct[col0 * 132 + r0]           = acc[ma][nb][0];
                Ct[(col0 + 1) * 132 + r0]     = acc[ma][nb][1];
                Ct[col0 * 132 + r0 + 8]       = acc[ma][nb][2];
                Ct[(col0 + 1) * 132 + r0 + 8] = acc[ma][nb][3];
            }
        }
        __syncthreads();
        for (int i = tid; i < 128 * 32; i += 256) {
            int col = i >> 5;
            int r4 = (i & 31) * 4;
            float4 v = *(float4*)&Ct[col * 132 + r4];
            *(float4*)(Yout + (size_t)(colBase + col) * 128 + r4) = v;
        }
    }
}

// ---------------------------------------------------------------------------
// SIMT SGEMM for mask-head conv (fp32 exact), stats fused
// ---------------------------------------------------------------------------
template<int RT>
__global__ void __launch_bounds__(256, 2) gemm_fused(
    const float* __restrict__ A, const float* __restrict__ B, float* __restrict__ C,
    int K, int Ncols, int statsLayer)
{
    constexpr int TM = RT * 16;
    __shared__ float As[2][16][TM + 4];
    __shared__ float Bs[2][16][128];
    const int tid = threadIdx.x;
    const int tx = tid & 15, ty = tid >> 4;
    const int rowBase = blockIdx.y * TM;
    const int colBase = blockIdx.x * 128;

    float acc[RT][8];
#pragma unroll
    for (int i = 0; i < RT; i++)
#pragma unroll
        for (int j = 0; j < 8; j++) acc[i][j] = 0.f;

    const int ktiles = K >> 4;
    {
#pragma unroll
        for (int l = 0; l < RT; l++) {
            int i = l * 256 + tid;
            int r = i >> 4, kk = i & 15;
            As[0][kk][r] = A[(rowBase + r) * K + kk];
        }
#pragma unroll
        for (int l = 0; l < 2; l++) {
            int i = l * 256 + tid;
            int kk = i >> 5, c4 = i & 31;
            int gc = colBase + c4 * 4;
            const float* src = B + (((size_t)(gc >> 14) * 128 + kk) << 14) + (gc & 16383);
            *(float4*)&Bs[0][kk][c4 * 4] = *(const float4*)src;
        }
    }
    __syncthreads();

    float pa[RT];
    float4 pb0, pb1;
    for (int kt = 0; kt < ktiles; kt++) {
        const int cur = kt & 1, nxt = cur ^ 1;
        const bool more = (kt + 1 < ktiles);
        if (more) {
            const int k0 = (kt + 1) << 4;
#pragma unroll
            for (int l = 0; l < RT; l++) {
                int i = l * 256 + tid;
                int r = i >> 4, kk = i & 15;
                pa[l] = A[(rowBase + r) * K + k0 + kk];
            }
#pragma unroll
            for (int l = 0; l < 2; l++) {
                int i = l * 256 + tid;
                int kk = i >> 5, c4 = i & 31;
                int gk = k0 + kk, gc = colBase + c4 * 4;
                const float* src = B + (((size_t)(gc >> 14) * 128 + gk) << 14) + (gc & 16383);
                float4 v = *(const float4*)src;
                if (l == 0) pb0 = v; else pb1 = v;
            }
        }
#pragma unroll
        for (int kk = 0; kk < 16; kk++) {
            float ra[RT], rb[8];
#pragma unroll
            for (int i = 0; i < RT; i++) ra[i] = As[cur][kk][ty * RT + i];
#pragma unroll
            for (int j = 0; j < 8; j++) rb[j] = Bs[cur][kk][tx * 8 + j];
#pragma unroll
            for (int i = 0; i < RT; i++)
#pragma unroll
                for (int j = 0; j < 8; j++)
                    acc[i][j] = fmaf(ra[i], rb[j], acc[i][j]);
        }
        if (more) {
#pragma unroll
            for (int l = 0; l < RT; l++) {
                int i = l * 256 + tid;
                int r = i >> 4, kk = i & 15;
                As[nxt][kk][r] = pa[l];
            }
            { int kk = tid >> 5, c4 = tid & 31; *(float4*)&Bs[nxt][kk][c4 * 4] = pb0; }
            { int i = 256 + tid; int kk = i >> 5, c4 = i & 31; *(float4*)&Bs[nxt][kk][c4 * 4] = pb1; }
        }
        __syncthreads();
    }
#pragma unroll
    for (int i = 0; i < RT; i++) {
        float* dst = C + (size_t)(rowBase + ty * RT + i) * Ncols + colBase + tx * 8;
        *(float4*)dst       = make_float4(acc[i][0], acc[i][1], acc[i][2], acc[i][3]);
        *(float4*)(dst + 4) = make_float4(acc[i][4], acc[i][5], acc[i][6], acc[i][7]);
    }
#pragma unroll
    for (int i = 0; i < RT; i++) {
        float s = 0.f, s2 = 0.f;
#pragma unroll
        for (int j = 0; j < 8; j++) { float v = acc[i][j]; s += v; s2 = fmaf(v, v, s2); }
#pragma unroll
        for (int off = 1; off < 16; off <<= 1) {
            s  += __shfl_xor_sync(0xFFFFFFFFu, s, off);
            s2 += __shfl_xor_sync(0xFFFFFFFFu, s2, off);
        }
        if (tx == 0) {
            int gr = rowBase + ty * RT + i;
            atomicAdd(&g_sum[statsLayer][gr], (double)s);
            atomicAdd(&g_sumsq[statsLayer][gr], (double)s2);
        }
    }
}

// ---------------------------------------------------------------------------
// mask head (BN0 finalize fused)
// ---------------------------------------------------------------------------
__global__ void maskhead_kernel(const float* __restrict__ y1d,
                                const float* __restrict__ fg1,
                                const float* __restrict__ fb1,
                                const float* __restrict__ fw2,
                                const float* __restrict__ fbias2,
                                float* __restrict__ outScores,
                                float* __restrict__ margin)
{
    __shared__ float affA[64], affC[64];
    if (threadIdx.x < 64)
        bn_affine(0, threadIdx.x, (double)NCOLS1D, fg1, fb1,
                  affA[threadIdx.x], affC[threadIdx.x]);
    __syncthreads();
    int col = blockIdx.x * blockDim.x + threadIdx.x;
    int b = col >> 14, n = col & 16383;
    float s0 = fbias2[0], s1 = fbias2[1];
#pragma unroll 4
    for (int c = 0; c < 64; c++) {
        float v = fmaxf(fmaf(affA[c], y1d[(size_t)c * NCOLS1D + col], affC[c]), 0.f);
        s0 = fmaf(fw2[c], v, s0);
        s1 = fmaf(fw2[64 + c], v, s1);
    }
    outScores[b * 32768 + n]         = s0;
    outScores[b * 32768 + 16384 + n] = s1;
    float mx = fmaxf(s0, s1);
    float e0 = expf(s0 - mx), e1 = expf(s1 - mx);
    margin[col] = (e1 - e0) / (e0 + e1);
}

// ---------------------------------------------------------------------------
// exact top-2048 per batch (radix select on 64-bit key)
// ---------------------------------------------------------------------------
__device__ __forceinline__ unsigned long long makeKey(float f, int i)
{
    unsigned u = __float_as_uint(f);
    u = (u & 0x80000000u) ? ~u : (u | 0x80000000u);
    return ((unsigned long long)u << 32) | (unsigned)(0xFFFFFFFFu - (unsigned)i);
}

__global__ void select_kernel(const float* __restrict__ margin, int* __restrict__ fgmask)
{
    __shared__ unsigned hist[256];
    __shared__ unsigned long long sprefix;
    __shared__ int skrem;
    int b = blockIdx.x, tid = threadIdx.x;
    const float* M = margin + b * NPTS;
    if (tid == 0) { sprefix = 0ull; skrem = TOPK_K; }
    __syncthreads();
    for (int pos = 56; pos >= 0; pos -= 8) {
        hist[tid] = 0;
        __syncthreads();
        unsigned long long pref = sprefix;
        for (int i = tid; i < NPTS; i += 256) {
            unsigned long long key = makeKey(M[i], i);
            bool act = (pos == 56) || ((key >> (pos + 8)) == (pref >> (pos + 8)));
            if (act) atomicAdd(&hist[(unsigned)(key >> pos) & 255u], 1u);
        }
        __syncthreads();
        if (tid == 0) {
            int k = skrem;
            int v = 255;
            while (v > 0 && (int)hist[v] < k) { k -= (int)hist[v]; v--; }
            skrem = k;
            sprefix = pref | ((unsigned long long)(unsigned)v << pos);
        }
        __syncthreads();
    }
    unsigned long long kth = sprefix;
    for (int i = tid; i < NPTS; i += 256)
        fgmask[b * NPTS + i] = (makeKey(M[i], i) >= kth) ? 1 : 0;
}

// ---------------------------------------------------------------------------
// masked FPS v2: Morton sort, 32 warps x 448-slot boxes, f32x2 packed math,
// early-exit inactive warps + named barriers. Exact (rn per-element).
// ---------------------------------------------------------------------------
#define WSLOT 448
#define NPAIR 7

__device__ __forceinline__ int spread3(int v) {
    return (v & 1) | ((v & 2) << 2) | ((v & 4) << 4);
}
__device__ __forceinline__ int cellOf(float x, float y, float z) {
    int cx = min(7, max(0, (int)(x * 8.f)));
    int cy = min(7, max(0, (int)(y * 8.f)));
    int cz = min(7, max(0, (int)(z * 8.f)));
    return spread3(cx) | (spread3(cy) << 1) | (spread3(cz) << 2);
}

__global__ void __launch_bounds__(1024, 1) fps_kernel(
    const float* __restrict__ xyz, const int* __restrict__ fgmask,
    int* __restrict__ fpsPid, int* __restrict__ idxInt, float* __restrict__ idxOutF)
{
    extern __shared__ float sh[];
    float* xs = sh;               // 14336
    float* ys = sh + 14336;
    float* zs = sh + 28672;
    __shared__ int hist[512];
    __shared__ uint2 warpRes[32];
    __shared__ float swx, swy, swz;

    const int blk = blockIdx.x, b = blk >> 1, isFg = !(blk & 1);
    const float* X = xyz + (size_t)b * NPTS * 3;
    const int* Mk = fgmask + b * NPTS;
    int* pidbuf = fpsPid + blk * 14336;
    const int tid = threadIdx.x, lane = tid & 31, wid = tid >> 5;
    const int cnt = isFg ? TOPK_K : (NPTS - TOPK_K);   // 2048 / 14336
    const int nwActive = isFg ? 5 : 32;
    const int padded = nwActive * WSLOT;               // 2240 / 14336
    const int nbar = nwActive * 32;

    // Morton histogram
    if (tid < 512) hist[tid] = 0;
    __syncthreads();
    for (int i = tid; i < NPTS; i += 1024) {
        int m = Mk[i]; if (!isFg) m = !m;
        if (m) atomicAdd(&hist[cellOf(X[i*3], X[i*3+1], X[i*3+2])], 1);
    }
    __syncthreads();
    // exclusive scan (scratch in xs)
    {
        int* sa = (int*)xs;
        int* sb = sa + 512;
        if (tid < 512) sa[tid] = hist[tid];
        __syncthreads();
        for (int off = 1; off < 512; off <<= 1) {
            int v = 0;
            if (tid < 512) v = sa[tid] + (tid >= off ? sa[tid - off] : 0);
            __syncthreads();
            if (tid < 512) sb[tid] = v;
            int* tp = sa; sa = sb; sb = tp;
            __syncthreads();
        }
        int excl = 0;
        if (tid < 512) excl = sa[tid] - hist[tid];
        __syncthreads();
        if (tid < 512) hist[tid] = excl;
    }
    __syncthreads();
    // scatter cell-sorted (SoA) + pid to gmem
    for (int i = tid; i < NPTS; i += 1024) {
        int m = Mk[i]; if (!isFg) m = !m;
        if (m) {
            float x = X[i*3], y = X[i*3+1], z = X[i*3+2];
            int pos = atomicAdd(&hist[cellOf(x, y, z)], 1);
            xs[pos] = x; ys[pos] = y; zs[pos] = z;
            pidbuf[pos] = i;
        }
    }
    __syncthreads();
    // pads: duplicate last real point (same pid -> exact)
    for (int i = cnt + tid; i < padded; i += 1024) {
        xs[i] = xs[cnt-1]; ys[i] = ys[cnt-1]; zs[i] = zs[cnt-1];
        pidbuf[i] = pidbuf[cnt-1];
    }
    __syncthreads();

    if (wid >= nwActive) {
        if (lane == 0) warpRes[wid] = make_uint2(0u, 0xFFFFFFFFu);
        return;
    }

    const int wbase = wid * WSLOT;
    const float2* xs2 = (const float2*)xs;
    const float2* ys2 = (const float2*)ys;
    const float2* zs2 = (const float2*)zs;
    const int pbase = (wbase >> 1) + lane;

    float mindL[NPAIR], mindH[NPAIR];
    uint32_t pkL[NPAIR], pkH[NPAIR];
    float bxl = 1e9f, bxh = -1e9f, byl = 1e9f, byh = -1e9f, bzl = 1e9f, bzh = -1e9f;
#pragma unroll
    for (int p = 0; p < NPAIR; p++) {
        int s0 = wbase + (p * 32 + lane) * 2;
        int2 pp = *(const int2*)&pidbuf[s0];
        pkL[p] = ((uint32_t)pp.x << 14) | (uint32_t)s0;
        pkH[p] = ((uint32_t)pp.y << 14) | (uint32_t)(s0 + 1);
        mindL[p] = 1e10f; mindH[p] = 1e10f;
        float2 xp = xs2[pbase + p * 32];
        float2 yp = ys2[pbase + p * 32];
        float2 zp = zs2[pbase + p * 32];
        bxl = fminf(bxl, fminf(xp.x, xp.y)); bxh = fmaxf(bxh, fmaxf(xp.x, xp.y));
        byl = fminf(byl, fminf(yp.x, yp.y)); byh = fmaxf(byh, fmaxf(yp.x, yp.y));
        bzl = fminf(bzl, fminf(zp.x, zp.y)); bzh = fmaxf(bzh, fmaxf(zp.x, zp.y));
    }
#pragma unroll
    for (int off = 16; off; off >>= 1) {
        bxl = fminf(bxl, __shfl_xor_sync(0xFFFFFFFFu, bxl, off));
        bxh = fmaxf(bxh, __shfl_xor_sync(0xFFFFFFFFu, bxh, off));
        byl = fminf(byl, __shfl_xor_sync(0xFFFFFFFFu, byl, off));
        byh = fmaxf(byh, __shfl_xor_sync(0xFFFFFFFFu, byh, off));
        bzl = fminf(bzl, __shfl_xor_sync(0xFFFFFFFFu, bzl, off));
        bzh = fmaxf(bzh, __shfl_xor_sync(0xFFFFFFFFu, bzh, off));
    }
    float bv = 1e10f;
    uint32_t bi = 0xFFFFFFFFu;
#pragma unroll
    for (int p = 0; p < NPAIR; p++) bi = min(bi, min(pkL[p], pkH[p]));

    const int outBase = b * NPOINT + (isFg ? 0 : FG_NS);
    for (int it = 0; it < FG_NS; it++) {
        uint32_t key = __float_as_uint(bv);
        uint32_t kmax = __reduce_max_sync(0xFFFFFFFFu, key);
        uint32_t cmin = __reduce_min_sync(0xFFFFFFFFu, (key == kmax) ? bi : 0xFFFFFFFFu);
        if (lane == 0) warpRes[wid] = make_uint2(kmax, cmin);
        asm volatile("bar.sync 1, %0;" :: "r"(nbar) : "memory");
        if (wid == 0) {
            uint2 e = warpRes[lane];
            uint32_t k2 = __reduce_max_sync(0xFFFFFFFFu, e.x);
            uint32_t c2 = __reduce_min_sync(0xFFFFFFFFu, (e.x == k2) ? e.y : 0xFFFFFFFFu);
            if (lane == 0) {
                int pid = (int)(c2 >> 14);
                int slot = (int)(c2 & 0x3FFFu);
                idxInt[outBase + it] = pid;
                idxOutF[outBase + it] = (float)pid;
                swx = xs[slot]; swy = ys[slot]; swz = zs[slot];
            }
        }
        asm volatile("bar.sync 1, %0;" :: "r"(nbar) : "memory");
        float sx = swx, sy = swy, sz = swz;
        float dxc = fmaxf(fmaxf(__fsub_rn(bxl, sx), __fsub_rn(sx, bxh)), 0.f);
        float dyc = fmaxf(fmaxf(__fsub_rn(byl, sy), __fsub_rn(sy, byh)), 0.f);
        float dzc = fmaxf(fmaxf(__fsub_rn(bzl, sz), __fsub_rn(sz, bzh)), 0.f);
        float LB = dxc * dxc + dyc * dyc + dzc * dzc;
        float LBm = LB * 0.999f - 1e-6f;     // down-biased: skip is exact
        if (!__all_sync(0xFFFFFFFFu, LBm >= bv)) {
            unsigned long long nsx = pk2(-sx, -sx);
            unsigned long long nsy = pk2(-sy, -sy);
            unsigned long long nsz = pk2(-sz, -sz);
            float nbv = 0.f;
#pragma unroll
            for (int p = 0; p < NPAIR; p++) {
                float2 xp = xs2[pbase + p * 32];
                float2 yp = ys2[pbase + p * 32];
                float2 zp = zs2[pbase + p * 32];
                unsigned long long dx2 = add2(pk2(xp.x, xp.y), nsx);
                unsigned long long dy2 = add2(pk2(yp.x, yp.y), nsy);
                unsigned long long dz2 = add2(pk2(zp.x, zp.y), nsz);
                unsigned long long d2 = add2(add2(mul2(dx2, dx2), mul2(dy2, dy2)),
                                             mul2(dz2, dz2));
                float d0, d1;
                upk2(d2, d0, d1);
                mindL[p] = fminf(mindL[p], d0);
                mindH[p] = fminf(mindH[p], d1);
                nbv = fmaxf(nbv, fmaxf(mindL[p], mindH[p]));
            }
            uint32_t nbi = 0xFFFFFFFFu;
#pragma unroll
            for (int p = 0; p < NPAIR; p++) {
                nbi = (mindL[p] == nbv) ? min(nbi, pkL[p]) : nbi;
                nbi = (mindH[p] == nbv) ? min(nbi, pkH[p]) : nbi;
            }
            bv = nbv;
            bi = nbi;
        }
    }
}

// ---------------------------------------------------------------------------
// ball query + fused centroid gather: one warp per query
// ---------------------------------------------------------------------------
__global__ void ballq_kernel(const float* __restrict__ xyz, const int* __restrict__ idxInt,
                             float* __restrict__ newxyz, float* __restrict__ outXyz,
                             int* __restrict__ ballIdx)
{
    __shared__ int lists[8][32];
    int warp = threadIdx.x >> 5, lane = threadIdx.x & 31;
    int q = blockIdx.x * 8 + warp;
    int b = q >> 10;
    const float* X = xyz + (size_t)b * NPTS * 3;
    int sel = idxInt[q];
    float qx = X[sel * 3], qy = X[sel * 3 + 1], qz = X[sel * 3 + 2];
    if (lane < 3) {
        float v = X[sel * 3 + lane];
        newxyz[q * 3 + lane] = v;
        outXyz[q * 3 + lane] = v;
    }
    const float R2 = (float)(0.3 * 0.3);
    int cnt = 0;
    for (int chunk = 0; chunk < NPTS / 32; chunk++) {
        int p = chunk * 32 + lane;
        float dx = __fsub_rn(qx, X[p * 3 + 0]);
        float dy = __fsub_rn(qy, X[p * 3 + 1]);
        float dz = __fsub_rn(qz, X[p * 3 + 2]);
        float d2 = __fadd_rn(__fadd_rn(__fmul_rn(dx, dx), __fmul_rn(dy, dy)),
                             __fmul_rn(dz, dz));
        bool in = (d2 <= R2);
        unsigned m = __ballot_sync(0xFFFFFFFFu, in);
        if (m) {
            int pos = cnt + __popc(m & ((1u << lane) - 1u));
            if (in && pos < 32) lists[warp][pos] = p;
            cnt += __popc(m);
            if (cnt >= 32) break;
        }
    }
    __syncwarp();
    int c = cnt < 32 ? cnt : 32;
    int v = (lane < c) ? lists[warp][lane] : lists[warp][0];
    ballIdx[q * 32 + lane] = v;
}

// ---------------------------------------------------------------------------
// build transposed grouped input xbufT[131072][160]; coalesced featT reads
// ---------------------------------------------------------------------------
__global__ void buildxT_kernel(const float* __restrict__ xyz, const float* __restrict__ featT,
                               const float* __restrict__ newxyz, const int* __restrict__ ballIdx,
                               float* __restrict__ xbufT)
{
    int warp = threadIdx.x >> 5, lane = threadIdx.x & 31;
    int col = blockIdx.x * 8 + warp;
    int b = col >> 15, s = (col >> 5) & 1023;
    int idx = ballIdx[col];
    const float* fr = featT + ((size_t)b * NPTS + idx) * CIN;
    float* dst = xbufT + (size_t)col * KX1;
#pragma unroll
    for (int it = 0; it < 5; it++) {
        int c = it * 32 + lane;
        float v = 0.f;
        if (c < 3)
            v = __fsub_rn(xyz[((size_t)b * NPTS + idx) * 3 + c],
                          newxyz[((b << 10) + s) * 3 + c]);
        else if (c < 131)
            v = fr[c - 3];
        dst[c] = v;
    }
}

// ---------------------------------------------------------------------------
// final maxpool (BN3 finalize fused)
// ---------------------------------------------------------------------------
__global__ void maxpool_final(const float* __restrict__ pmax, const float* __restrict__ pmin,
                              const float* __restrict__ g3, const float* __restrict__ b3,
                              float* __restrict__ outFeat)
{
    __shared__ float sa_, sc_;
    int t = blockIdx.x * blockDim.x + threadIdx.x;   // 1048576
    int m = t >> 12;
    if (threadIdx.x == 0) bn_affine(3, m, (double)NCOLS2D, g3, b3, sa_, sc_);
    __syncthreads();
    float a = sa_, c = sc_;
    int cent = t & 4095;
    float y = (a >= 0.f) ? pmax[t] : pmin[t];
    float v = fmaxf(fmaf(a, y, c), 0.f);
    int b = cent >> 10, s = cent & 1023;
    outFeat[(((size_t)b * 256 + m) << 10) + s] = v;
}

// ---------------------------------------------------------------------------
extern "C" void kernel_launch(void* const* d_in, const int* in_sizes, int n_in,
                              void* d_out, int out_size)
{
    const float* xyz      = (const float*)d_in[0];
    const float* features = (const float*)d_in[1];
    const float* w1  = (const float*)d_in[2];
    const float* g1  = (const float*)d_in[3];
    const float* b1  = (const float*)d_in[4];
    const float* w2  = (const float*)d_in[5];
    const float* g2  = (const float*)d_in[6];
    const float* b2  = (const float*)d_in[7];
    const float* w3  = (const float*)d_in[8];
    const float* g3  = (const float*)d_in[9];
    const float* b3  = (const float*)d_in[10];
    const float* fw1 = (const float*)d_in[11];
    const float* fg1 = (const float*)d_in[12];
    const float* fb1 = (const float*)d_in[13];
    const float* fw2 = (const float*)d_in[14];
    const float* fbias2 = (const float*)d_in[15];

    float* out = (float*)d_out;
    float* outXyz    = out + OFS_XYZ;
    float* outFeat   = out + OFS_FEAT;
    float* outIdx    = out + OFS_IDX;
    float* outScores = out + OFS_SCORES;

    float* scr = nullptr;
    cudaGetSymbolAddress((void**)&scr, g_scratch);
    float* y1d    = scr + O_Y1D;
    float* xbufT  = scr + O_XT;
    float* y1T    = scr + O_Y1T;
    float* y2T    = scr + O_Y2T;
    float* p3max  = scr + O_P3MAX;
    float* p3min  = scr + O_P3MIN;
    float* margin = scr + O_MARGIN;
    float* newxyz = scr + O_NEWXYZ;
    float* wpad   = scr + O_WPAD;
    float* featT  = scr + O_FEATT;
    int* fgmask   = (int*)(scr + O_FGMASK);
    int* idxInt   = (int*)(scr + O_INDICES);
    int* ballIdx  = (int*)(scr + O_BALL);
    int* fpsPid   = (int*)(scr + O_FPSPID);

    prep_kernel<<<80, 256>>>(w1, wpad);
    transpose_kernel<<<dim3(NPTS / 32, CIN / 32, BATCH), dim3(32, 8)>>>(features, featT);

    gemm_fused<4><<<dim3(NCOLS1D / 128, 1), 256>>>(fw1, features, y1d, 128, NCOLS1D, 0);
    maskhead_kernel<<<NCOLS1D / 256, 256>>>(y1d, fg1, fb1, fw2, fbias2, outScores, margin);
    select_kernel<<<4, 256>>>(margin, fgmask);

    cudaFuncSetAttribute(fps_kernel, cudaFuncAttributeMaxDynamicSharedMemorySize, 14336 * 12);
    fps_kernel<<<8, 1024, 14336 * 12>>>(xyz, fgmask, fpsPid, idxInt, outIdx);

    ballq_kernel<<<NPOINT * BATCH / 8, 256>>>(xyz, idxInt, newxyz, outXyz, ballIdx);
    buildxT_kernel<<<NCOLS2D / 8, 256>>>(xyz, featT, newxyz, ballIdx, xbufT);

    {
        auto k = conv_mma<KX1, -1, 1, 0>;
        size_t sm = (size_t)2 * 128 * (KX1 + 4) * 4;
        cudaFuncSetAttribute(k, cudaFuncAttributeMaxDynamicSharedMemorySize, (int)sm);
        k<<<dim3(NCOLS2D / 128, 1), 256, sm>>>(wpad, xbufT, y1T, nullptr, nullptr,
                                               nullptr, nullptr);
    }
    {
        auto k = conv_mma<128, 1, 2, 0>;
        size_t sm = (size_t)2 * 128 * 132 * 4;
        cudaFuncSetAttribute(k, cudaFuncAttributeMaxDynamicSharedMemorySize, (int)sm);
        k<<<dim3(NCOLS2D / 128, 1), 256, sm>>>(w2, y1T, y2T, nullptr, nullptr, g1, b1);
    }
    {
        auto k = conv_mma<128, 2, 3, 1>;
        size_t sm = (size_t)2 * 128 * 132 * 4;
        cudaFuncSetAttribute(k, cudaFuncAttributeMaxDynamicSharedMemorySize, (int)sm);
        k<<<dim3(NCOLS2D / 128, 2), 256, sm>>>(w3, y2T, nullptr, p3max, p3min, g2, b2);
    }
    maxpool_final<<<(256 * 4096) / 256, 256>>>(p3max, p3min, g3, b3, outFeat);
}